// round 10
// baseline (speedup 1.0000x reference)
#include <cuda_runtime.h>
#include <cuda_bf16.h>
#include <cstdint>

#define BB   16
#define CIN  64
#define COUT 64
#define NN   1024
#define LL   12
#define CL   768   // COUT*LL

// ------------------- device scratch (allocation-free) -------------------
__device__ float g_f  [(size_t)BB * NN];
__device__ float g_mx [(size_t)BB * NN];
__device__ float g_si [(size_t)BB * NN];
__device__ __nv_bfloat16 g_Ahi[(size_t)BB * NN * NN];   // [b][q][n]   (GEMM A, K-contig)
__device__ __nv_bfloat16 g_Alo[(size_t)BB * NN * NN];
__device__ __nv_bfloat16 g_Xhi[(size_t)BB * CL * NN];   // [b][cl][n]  (GEMM B^T, K-contig)
__device__ __nv_bfloat16 g_Xlo[(size_t)BB * CL * NN];

// ------------------- PTX helpers -------------------
__device__ __forceinline__ uint32_t smem_u32(const void* p) {
    uint32_t a;
    asm("{ .reg .u64 t; cvta.to.shared.u64 t, %1; cvt.u32.u64 %0, t; }" : "=r"(a) : "l"(p));
    return a;
}
__device__ __forceinline__ void cp16(uint32_t dst, const void* src) {
    asm volatile("cp.async.cg.shared.global [%0], [%1], 16;" :: "r"(dst), "l"(src));
}
__device__ __forceinline__ void cp_commit() {
    asm volatile("cp.async.commit_group;" ::: "memory");
}
__device__ __forceinline__ void cp_wait1() {
    asm volatile("cp.async.wait_group 1;" ::: "memory");
}
__device__ __forceinline__ void ldsm4(uint32_t* r, uint32_t addr) {
    asm volatile("ldmatrix.sync.aligned.m8n8.x4.shared.b16 {%0,%1,%2,%3}, [%4];"
                 : "=r"(r[0]), "=r"(r[1]), "=r"(r[2]), "=r"(r[3]) : "r"(addr));
}
__device__ __forceinline__ void mma16816(float* d, const uint32_t* a, const uint32_t* bf) {
    asm volatile(
        "mma.sync.aligned.m16n8k16.row.col.f32.bf16.bf16.f32 "
        "{%0,%1,%2,%3}, {%4,%5,%6,%7}, {%8,%9}, {%0,%1,%2,%3};"
        : "+f"(d[0]), "+f"(d[1]), "+f"(d[2]), "+f"(d[3])
        : "r"(a[0]), "r"(a[1]), "r"(a[2]), "r"(a[3]), "r"(bf[0]), "r"(bf[1]));
}
// packed f32x2 (sm_100+): FFMA2
__device__ __forceinline__ unsigned long long pk2(float a, float b) {
    unsigned long long r;
    asm("mov.b64 %0, {%1, %2};" : "=l"(r) : "f"(a), "f"(b));
    return r;
}
__device__ __forceinline__ void fma2(unsigned long long& d, unsigned long long a, unsigned long long b) {
    asm("fma.rn.f32x2 %0, %1, %2, %0;" : "+l"(d) : "l"(a), "l"(b));
}
__device__ __forceinline__ void upk2(float& x, float& y, unsigned long long v) {
    asm("mov.b64 {%0, %1}, %2;" : "=f"(x), "=f"(y) : "l"(v));
}

// ------------------------------------------------------------------
// Kernel 1: conv0 (1x3, pad 1 on L) + bias; writes bf16 hi/lo X^T and f
// inner loop in packed f32x2 FMA
// ------------------------------------------------------------------
#define NT 16
#define WPITCH 65
#define PPITCH 897   // 64*14 + 1

__global__ __launch_bounds__(256) void conv_kernel(
    const float* __restrict__ in, const float* __restrict__ w0,
    const float* __restrict__ b0, const float* __restrict__ w1)
{
    extern __shared__ float sm[];
    float* Wsh = sm;
    float* Psh = sm + 192 * WPITCH;
    float* red = Psh + NT * PPITCH;

    int blk = blockIdx.x;
    int b   = blk >> 6;
    int n0  = (blk & 63) * NT;
    int tid = threadIdx.x;

    for (int idx = tid; idx < COUT * 192; idx += 256) {
        int cout = idx / 192, r = idx % 192;
        Wsh[r * WPITCH + cout] = w0[idx];
    }
    for (int idx = tid; idx < NT * CIN * 2; idx += 256) {
        int nt = idx >> 7; int r = idx & 127; int cin = r >> 1; int side = r & 1;
        Psh[nt * PPITCH + cin * 14 + side * 13] = 0.f;
    }
    const float* inb = in + (size_t)b * CIN * NN * LL;
    for (int idx = tid; idx < NT * CIN * LL; idx += 256) {
        int cin = idx / (NT * LL); int r = idx % (NT * LL);
        int nt = r / LL; int l = r % LL;
        Psh[nt * PPITCH + cin * 14 + l + 1] = inb[((size_t)cin * NN + n0 + nt) * LL + l];
    }
    __syncthreads();

    int cg = tid >> 4, nt = tid & 15;
    unsigned long long acc2[4][6];
    #pragma unroll
    for (int u = 0; u < 4; u++) {
        float bv = b0[cg * 4 + u];
        unsigned long long bb = pk2(bv, bv);
        #pragma unroll
        for (int j = 0; j < 6; j++) acc2[u][j] = bb;
    }
    const float* prow = Psh + nt * PPITCH;
    for (int cin = 0; cin < CIN; cin++) {
        float pv[14];
        #pragma unroll
        for (int x = 0; x < 14; x++) pv[x] = prow[cin * 14 + x];
        unsigned long long P0[7], P1[6];
        #pragma unroll
        for (int j = 0; j < 7; j++) P0[j] = pk2(pv[2 * j], pv[2 * j + 1]);
        #pragma unroll
        for (int j = 0; j < 6; j++) P1[j] = pk2(pv[2 * j + 1], pv[2 * j + 2]);
        #pragma unroll
        for (int kt = 0; kt < 3; kt++) {
            #pragma unroll
            for (int u = 0; u < 4; u++) {
                float wv = Wsh[(cin * 3 + kt) * WPITCH + cg * 4 + u];
                unsigned long long wv2 = pk2(wv, wv);
                #pragma unroll
                for (int j = 0; j < 6; j++) {
                    unsigned long long pvp = (kt == 0) ? P0[j] : (kt == 1 ? P1[j] : P0[j + 1]);
                    fma2(acc2[u][j], wv2, pvp);
                }
            }
        }
    }
    float acc[4][12];
    #pragma unroll
    for (int u = 0; u < 4; u++)
        #pragma unroll
        for (int j = 0; j < 6; j++) upk2(acc[u][2 * j], acc[u][2 * j + 1], acc2[u][j]);

    size_t xbase = (size_t)b * CL * NN;
    float fp = 0.f;
    #pragma unroll
    for (int u = 0; u < 4; u++) {
        int c = cg * 4 + u;
        #pragma unroll
        for (int l = 0; l < 12; l++) {
            float v = acc[u][l];
            int cl = c * 12 + l;
            __nv_bfloat16 h = __float2bfloat16(v);
            g_Xhi[xbase + (size_t)cl * NN + n0 + nt] = h;
            g_Xlo[xbase + (size_t)cl * NN + n0 + nt] = __float2bfloat16(v - __bfloat162float(h));
            fp += v * __ldg(&w1[cl]);
        }
    }
    red[nt * 16 + cg] = fp;
    __syncthreads();
    if (cg == 0) {
        float s = 0.f;
        #pragma unroll
        for (int k = 0; k < 16; k++) s += red[nt * 16 + k];
        g_f[b * NN + n0 + nt] = s;
    }
}

// ------------------------------------------------------------------
// Kernel 2a: row stats (max, inverse sum) of z = leaky(f_i+f_j)+adj
// ------------------------------------------------------------------
__global__ __launch_bounds__(256) void stats_kernel(const float* __restrict__ adj)
{
    int row = blockIdx.x;
    int b = row >> 10;
    int tid = threadIdx.x;
    const float* arow = adj + (size_t)row * NN;
    const float* fb = g_f + b * NN;
    float fi = fb[row & 1023];

    float zv[4]; float mx = -1e30f;
    #pragma unroll
    for (int k = 0; k < 4; k++) {
        int j = tid + k * 256;
        float lg = fi + fb[j];
        float z = (lg >= 0.f ? lg : 0.2f * lg) + arow[j];
        zv[k] = z; mx = fmaxf(mx, z);
    }
    __shared__ float sred[32];
    #pragma unroll
    for (int o = 16; o > 0; o >>= 1) mx = fmaxf(mx, __shfl_xor_sync(0xffffffffu, mx, o));
    if ((tid & 31) == 0) sred[tid >> 5] = mx;
    __syncthreads();
    if (tid < 32) {
        float v = (tid < 8) ? sred[tid] : -1e30f;
        #pragma unroll
        for (int o = 4; o > 0; o >>= 1) v = fmaxf(v, __shfl_xor_sync(0xffffffffu, v, o));
        if (tid == 0) sred[0] = v;
    }
    __syncthreads();
    mx = sred[0];
    __syncthreads();

    float s = 0.f;
    #pragma unroll
    for (int k = 0; k < 4; k++) s += __expf(zv[k] - mx);
    #pragma unroll
    for (int o = 16; o > 0; o >>= 1) s += __shfl_xor_sync(0xffffffffu, s, o);
    if ((tid & 31) == 0) sred[tid >> 5] = s;
    __syncthreads();
    if (tid < 32) {
        float v = (tid < 8) ? sred[tid] : 0.f;
        #pragma unroll
        for (int o = 4; o > 0; o >>= 1) v += __shfl_xor_sync(0xffffffffu, v, o);
        if (tid == 0) { g_mx[row] = mx; g_si[row] = 1.f / v; }
    }
}

// ------------------------------------------------------------------
// Kernel 2b: emit P tiles: bf16 hi/lo [i][j] + f32 attention output [j][i]
// ------------------------------------------------------------------
__global__ __launch_bounds__(256) void emit_kernel(
    const float* __restrict__ adj, float* __restrict__ outAtt)
{
    __shared__ float pt[32][33];
    int b  = blockIdx.z;
    int i0 = blockIdx.y * 32;
    int j0 = blockIdx.x * 32;
    int tid = threadIdx.x;
    int ii = tid >> 3, jt = tid & 7;

    const float* fb = g_f + b * NN;
    int irow = (b << 10) + i0 + ii;
    float fi = fb[i0 + ii];
    float mx = g_mx[irow];
    float si = g_si[irow];

    float4 av = *(const float4*)&adj[((size_t)irow) * NN + j0 + jt * 4];
    float p[4];
    #pragma unroll
    for (int e = 0; e < 4; e++) {
        int j = j0 + jt * 4 + e;
        float lg = fi + fb[j];
        float z = (lg >= 0.f ? lg : 0.2f * lg) + ((const float*)&av)[e];
        p[e] = __expf(z - mx) * si;
        pt[ii][jt * 4 + e] = p[e];
    }
    size_t rb = ((size_t)irow) * NN + j0 + jt * 4;
    uint2 hv, lv;
    __nv_bfloat16 h0 = __float2bfloat16(p[0]), h1 = __float2bfloat16(p[1]);
    __nv_bfloat16 h2 = __float2bfloat16(p[2]), h3 = __float2bfloat16(p[3]);
    hv.x = ((uint32_t)*(uint16_t*)&h1 << 16) | *(uint16_t*)&h0;
    hv.y = ((uint32_t)*(uint16_t*)&h3 << 16) | *(uint16_t*)&h2;
    __nv_bfloat16 l0 = __float2bfloat16(p[0] - __bfloat162float(h0));
    __nv_bfloat16 l1 = __float2bfloat16(p[1] - __bfloat162float(h1));
    __nv_bfloat16 l2 = __float2bfloat16(p[2] - __bfloat162float(h2));
    __nv_bfloat16 l3 = __float2bfloat16(p[3] - __bfloat162float(h3));
    lv.x = ((uint32_t)*(uint16_t*)&l1 << 16) | *(uint16_t*)&l0;
    lv.y = ((uint32_t)*(uint16_t*)&l3 << 16) | *(uint16_t*)&l2;
    *(uint2*)&g_Ahi[rb] = hv;
    *(uint2*)&g_Alo[rb] = lv;

    __syncthreads();
    int jj = tid >> 3, it = tid & 7;
    float4 ov;
    ov.x = pt[it * 4 + 0][jj];
    ov.y = pt[it * 4 + 1][jj];
    ov.z = pt[it * 4 + 2][jj];
    ov.w = pt[it * 4 + 3][jj];
    *(float4*)&outAtt[(((size_t)(b << 10) + j0 + jj)) * NN + i0 + it * 4] = ov;
}

// ------------------------------------------------------------------
// Kernel 3: HMMA (mma.sync bf16) 3-term split GEMM, 2 CTAs/SM
// single sync per chunk; term-reordered MMA issue (reuse distance 4)
// ------------------------------------------------------------------
#define STAGE_BYTES (32 * 1024)
#define XT_OFF      (16 * 1024)
#define NCHUNK      32

__device__ __forceinline__ void issue_stage(uint32_t sb,
    const __nv_bfloat16* Ah, const __nv_bfloat16* Al,
    const __nv_bfloat16* Xh, const __nv_bfloat16* Xl,
    int k0, int tid)
{
    int cm = tid >> 3;
    int cu = tid & 7;
    bool isHi = cu < 4;
    int kc = (isHi ? cu : cu - 4) * 8;
    #pragma unroll
    for (int r = 0; r < 4; r++) {
        int m = cm + 32 * r;
        uint32_t sw = (uint32_t)((cu ^ (m & 7)) << 4);
        const __nv_bfloat16* srcA = (isHi ? Ah : Al) + (size_t)m * NN + k0 + kc;
        const __nv_bfloat16* srcX = (isHi ? Xh : Xl) + (size_t)m * NN + k0 + kc;
        cp16(sb + m * 128 + sw, srcA);
        cp16(sb + XT_OFF + m * 128 + sw, srcX);
    }
}

__global__ __launch_bounds__(256, 2) void gemm_hmma_kernel(float* __restrict__ out)
{
    extern __shared__ char smc[];
    int tid  = threadIdx.x;
    int lane = tid & 31, w = tid >> 5;
    int b  = blockIdx.z;
    int n0 = blockIdx.x * 128;
    int m0 = blockIdx.y * 128;

    const __nv_bfloat16* Ah = g_Ahi + ((size_t)(b * NN + m0)) * NN;
    const __nv_bfloat16* Al = g_Alo + ((size_t)(b * NN + m0)) * NN;
    const __nv_bfloat16* Xh = g_Xhi + ((size_t)(b * CL + n0)) * NN;
    const __nv_bfloat16* Xl = g_Xlo + ((size_t)(b * CL + n0)) * NN;

    uint32_t smb = smem_u32(smc);

    issue_stage(smb, Ah, Al, Xh, Xl, 0, tid);
    cp_commit();
    issue_stage(smb + STAGE_BYTES, Ah, Al, Xh, Xl, 32, tid);
    cp_commit();

    int wm = (w & 3) * 32;
    int wn = (w >> 2) * 64;

    float acc[2][8][4];
    #pragma unroll
    for (int t = 0; t < 2; t++)
        #pragma unroll
        for (int bk = 0; bk < 8; bk++)
            #pragma unroll
            for (int e = 0; e < 4; e++) acc[t][bk][e] = 0.f;

    int ai  = lane & 15, ahf = lane >> 4;
    int xcb = (lane >> 4) & 1, xkh = (lane >> 3) & 1, xc7 = lane & 7;

    for (int t = 0; t < NCHUNK; t++) {
        cp_wait1();
        __syncthreads();
        if (t + 2 < NCHUNK)
            issue_stage(smb + ((t + 2) % 3) * STAGE_BYTES, Ah, Al, Xh, Xl, (t + 2) * 32, tid);
        cp_commit();

        uint32_t sa = smb + (t % 3) * STAGE_BYTES;
        uint32_t sx = sa + XT_OFF;

        #pragma unroll
        for (int s = 0; s < 2; s++) {
            uint32_t ah[2][4], al[2][4];
            #pragma unroll
            for (int mt = 0; mt < 2; mt++) {
                int row = wm + mt * 16 + ai;
                int cuH = 2 * s + ahf;
                ldsm4(ah[mt], sa + row * 128 + ((cuH ^ (row & 7)) << 4));
                ldsm4(al[mt], sa + row * 128 + (((cuH + 4) ^ (row & 7)) << 4));
            }
            #pragma unroll
            for (int g = 0; g < 4; g++) {
                uint32_t xh[4], xl[4];
                int col = wn + g * 16 + xcb * 8 + xc7;
                int cuH = 2 * s + xkh;
                ldsm4(xh, sx + col * 128 + ((cuH ^ (col & 7)) << 4));
                ldsm4(xl, sx + col * 128 + (((cuH + 4) ^ (col & 7)) << 4));
                // term-ordered issue: same-acc reuse distance = 4
                #pragma unroll
                for (int mt = 0; mt < 2; mt++) {
                    mma16816(acc[mt][2 * g],     ah[mt], &xh[0]);
                    mma16816(acc[mt][2 * g + 1], ah[mt], &xh[2]);
                }
                #pragma unroll
                for (int mt = 0; mt < 2; mt++) {
                    mma16816(acc[mt][2 * g],     al[mt], &xh[0]);
                    mma16816(acc[mt][2 * g + 1], al[mt], &xh[2]);
                }
                #pragma unroll
                for (int mt = 0; mt < 2; mt++) {
                    mma16816(acc[mt][2 * g],     ah[mt], &xl[0]);
                    mma16816(acc[mt][2 * g + 1], ah[mt], &xl[2]);
                }
            }
        }
        // no trailing sync: next iteration's top sync orders buffer reuse
    }

    float* ob = out + (size_t)b * COUT * NN * LL;
    int g8 = lane >> 2, t4 = lane & 3;
    #pragma unroll
    for (int mt = 0; mt < 2; mt++) {
        int q0 = m0 + wm + mt * 16 + g8;
        #pragma unroll
        for (int bk = 0; bk < 8; bk++) {
            int cl0 = n0 + wn + bk * 8 + t4 * 2;
            #pragma unroll
            for (int e = 0; e < 4; e++) {
                int q  = q0 + (e >> 1) * 8;
                int cl = cl0 + (e & 1);
                int c = cl / 12, l = cl - c * 12;
                ob[(size_t)c * (NN * LL) + q * 12 + l] = acc[mt][bk][e];
            }
        }
    }
}

// ------------------------------------------------------------------
extern "C" void kernel_launch(void* const* d_in, const int* in_sizes, int n_in,
                              void* d_out, int out_size)
{
    const float* in  = (const float*)d_in[0];
    const float* adj = (const float*)d_in[1];
    const float* w0  = (const float*)d_in[2];
    const float* b0  = (const float*)d_in[3];
    const float* w1  = (const float*)d_in[4];

    float* out    = (float*)d_out;
    float* hprime = out;
    float* att    = out + (size_t)BB * COUT * NN * LL;

    int convSmem = (192 * WPITCH + NT * PPITCH + 256) * (int)sizeof(float);
    cudaFuncSetAttribute(conv_kernel, cudaFuncAttributeMaxDynamicSharedMemorySize, convSmem);
    cudaFuncSetAttribute(gemm_hmma_kernel, cudaFuncAttributeMaxDynamicSharedMemorySize, 3 * STAGE_BYTES);

    conv_kernel<<<BB * (NN / NT), 256, convSmem>>>(in, w0, b0, w1);
    stats_kernel<<<BB * NN, 256>>>(adj);
    emit_kernel<<<dim3(NN / 32, NN / 32, BB), 256>>>(adj, att);
    gemm_hmma_kernel<<<dim3(CL / 128, NN / 128, BB), 256, 3 * STAGE_BYTES>>>(hprime);
}

// round 11
// speedup vs baseline: 1.0100x; 1.0100x over previous
#include <cuda_runtime.h>
#include <cuda_bf16.h>
#include <cstdint>

#define BB   16
#define CIN  64
#define COUT 64
#define NN   1024
#define LL   12
#define CL   768   // COUT*LL

// ------------------- device scratch (allocation-free) -------------------
__device__ float g_f  [(size_t)BB * NN];
__device__ float g_mx [(size_t)BB * NN];
__device__ float g_si [(size_t)BB * NN];
__device__ __nv_bfloat16 g_Ahi[(size_t)BB * NN * NN];   // [b][q][n]   (GEMM A, K-contig)
__device__ __nv_bfloat16 g_Alo[(size_t)BB * NN * NN];
__device__ __nv_bfloat16 g_Xhi[(size_t)BB * CL * NN];   // [b][cl][n]  (GEMM B^T, K-contig)
__device__ __nv_bfloat16 g_Xlo[(size_t)BB * CL * NN];

// ------------------- PTX helpers -------------------
__device__ __forceinline__ uint32_t smem_u32(const void* p) {
    uint32_t a;
    asm("{ .reg .u64 t; cvta.to.shared.u64 t, %1; cvt.u32.u64 %0, t; }" : "=r"(a) : "l"(p));
    return a;
}
__device__ __forceinline__ void cp16(uint32_t dst, const void* src) {
    asm volatile("cp.async.cg.shared.global [%0], [%1], 16;" :: "r"(dst), "l"(src));
}
__device__ __forceinline__ void cp_commit() {
    asm volatile("cp.async.commit_group;" ::: "memory");
}
__device__ __forceinline__ void cp_wait1() {
    asm volatile("cp.async.wait_group 1;" ::: "memory");
}
__device__ __forceinline__ void ldsm4(uint32_t* r, uint32_t addr) {
    asm volatile("ldmatrix.sync.aligned.m8n8.x4.shared.b16 {%0,%1,%2,%3}, [%4];"
                 : "=r"(r[0]), "=r"(r[1]), "=r"(r[2]), "=r"(r[3]) : "r"(addr));
}
__device__ __forceinline__ void mma16816(float* d, const uint32_t* a, const uint32_t* bf) {
    asm volatile(
        "mma.sync.aligned.m16n8k16.row.col.f32.bf16.bf16.f32 "
        "{%0,%1,%2,%3}, {%4,%5,%6,%7}, {%8,%9}, {%0,%1,%2,%3};"
        : "+f"(d[0]), "+f"(d[1]), "+f"(d[2]), "+f"(d[3])
        : "r"(a[0]), "r"(a[1]), "r"(a[2]), "r"(a[3]), "r"(bf[0]), "r"(bf[1]));
}
// packed f32x2 (sm_100+): FFMA2
__device__ __forceinline__ unsigned long long pk2(float a, float b) {
    unsigned long long r;
    asm("mov.b64 %0, {%1, %2};" : "=l"(r) : "f"(a), "f"(b));
    return r;
}
__device__ __forceinline__ void fma2(unsigned long long& d, unsigned long long a, unsigned long long b) {
    asm("fma.rn.f32x2 %0, %1, %2, %0;" : "+l"(d) : "l"(a), "l"(b));
}
__device__ __forceinline__ void upk2(float& x, float& y, unsigned long long v) {
    asm("mov.b64 {%0, %1}, %2;" : "=f"(x), "=f"(y) : "l"(v));
}

// ------------------------------------------------------------------
// Kernel 1: conv0 (1x3, pad 1 on L) + bias; writes bf16 hi/lo X^T and f
// FFMA2 inner loop; vectorized LDS (7x LDS.64 patches, 3x LDS.128 weights)
// ------------------------------------------------------------------
#define NT 16
#define WPITCH 68    // 16B-aligned rows -> float4 weight reads
#define PPITCH 898   // 8B-aligned rows  -> float2 patch reads (64*14 + 2)

__global__ __launch_bounds__(256) void conv_kernel(
    const float* __restrict__ in, const float* __restrict__ w0,
    const float* __restrict__ b0, const float* __restrict__ w1)
{
    extern __shared__ float sm[];
    float* Wsh = sm;                        // [192][WPITCH] : [cin*3+kt][cout]
    float* Psh = sm + 192 * WPITCH;         // [NT][PPITCH]  : [nt][cin*14 + x]
    float* red = Psh + NT * PPITCH;

    int blk = blockIdx.x;
    int b   = blk >> 6;
    int n0  = (blk & 63) * NT;
    int tid = threadIdx.x;

    for (int idx = tid; idx < COUT * 192; idx += 256) {
        int cout = idx / 192, r = idx % 192;
        Wsh[r * WPITCH + cout] = w0[idx];
    }
    for (int idx = tid; idx < NT * CIN * 2; idx += 256) {
        int nt = idx >> 7; int r = idx & 127; int cin = r >> 1; int side = r & 1;
        Psh[nt * PPITCH + cin * 14 + side * 13] = 0.f;
    }
    const float* inb = in + (size_t)b * CIN * NN * LL;
    for (int idx = tid; idx < NT * CIN * LL; idx += 256) {
        int cin = idx / (NT * LL); int r = idx % (NT * LL);
        int nt = r / LL; int l = r % LL;
        Psh[nt * PPITCH + cin * 14 + l + 1] = inb[((size_t)cin * NN + n0 + nt) * LL + l];
    }
    __syncthreads();

    int cg = tid >> 4, nt = tid & 15;
    unsigned long long acc2[4][6];
    #pragma unroll
    for (int u = 0; u < 4; u++) {
        float bv = b0[cg * 4 + u];
        unsigned long long bb = pk2(bv, bv);
        #pragma unroll
        for (int j = 0; j < 6; j++) acc2[u][j] = bb;
    }
    const float2* prow2 = (const float2*)(Psh + nt * PPITCH);   // PPITCH even -> aligned
    for (int cin = 0; cin < CIN; cin++) {
        // 7 x LDS.64 : pv pairs (pv[2j], pv[2j+1])
        unsigned long long P0[7];
        float pv[14];
        #pragma unroll
        for (int j = 0; j < 7; j++) {
            float2 v = prow2[cin * 7 + j];
            pv[2 * j] = v.x; pv[2 * j + 1] = v.y;
            P0[j] = pk2(v.x, v.y);
        }
        unsigned long long P1[6];
        #pragma unroll
        for (int j = 0; j < 6; j++) P1[j] = pk2(pv[2 * j + 1], pv[2 * j + 2]);
        #pragma unroll
        for (int kt = 0; kt < 3; kt++) {
            // 1 x LDS.128 : 4 couts
            float4 wv4 = *(const float4*)&Wsh[(cin * 3 + kt) * WPITCH + cg * 4];
            const float* wv = (const float*)&wv4;
            #pragma unroll
            for (int u = 0; u < 4; u++) {
                unsigned long long wv2 = pk2(wv[u], wv[u]);
                #pragma unroll
                for (int j = 0; j < 6; j++) {
                    unsigned long long pvp = (kt == 0) ? P0[j] : (kt == 1 ? P1[j] : P0[j + 1]);
                    fma2(acc2[u][j], wv2, pvp);
                }
            }
        }
    }
    float acc[4][12];
    #pragma unroll
    for (int u = 0; u < 4; u++)
        #pragma unroll
        for (int j = 0; j < 6; j++) upk2(acc[u][2 * j], acc[u][2 * j + 1], acc2[u][j]);

    size_t xbase = (size_t)b * CL * NN;
    float fp = 0.f;
    #pragma unroll
    for (int u = 0; u < 4; u++) {
        int c = cg * 4 + u;
        #pragma unroll
        for (int l = 0; l < 12; l++) {
            float v = acc[u][l];
            int cl = c * 12 + l;
            __nv_bfloat16 h = __float2bfloat16(v);
            g_Xhi[xbase + (size_t)cl * NN + n0 + nt] = h;
            g_Xlo[xbase + (size_t)cl * NN + n0 + nt] = __float2bfloat16(v - __bfloat162float(h));
            fp += v * __ldg(&w1[cl]);
        }
    }
    red[nt * 16 + cg] = fp;
    __syncthreads();
    if (cg == 0) {
        float s = 0.f;
        #pragma unroll
        for (int k = 0; k < 16; k++) s += red[nt * 16 + k];
        g_f[b * NN + n0 + nt] = s;
    }
}

// ------------------------------------------------------------------
// Kernel 2a: row stats (max, inverse sum) of z = leaky(f_i+f_j)+adj
// ------------------------------------------------------------------
__global__ __launch_bounds__(256) void stats_kernel(const float* __restrict__ adj)
{
    int row = blockIdx.x;
    int b = row >> 10;
    int tid = threadIdx.x;
    const float* arow = adj + (size_t)row * NN;
    const float* fb = g_f + b * NN;
    float fi = fb[row & 1023];

    float zv[4]; float mx = -1e30f;
    #pragma unroll
    for (int k = 0; k < 4; k++) {
        int j = tid + k * 256;
        float lg = fi + fb[j];
        float z = (lg >= 0.f ? lg : 0.2f * lg) + arow[j];
        zv[k] = z; mx = fmaxf(mx, z);
    }
    __shared__ float sred[32];
    #pragma unroll
    for (int o = 16; o > 0; o >>= 1) mx = fmaxf(mx, __shfl_xor_sync(0xffffffffu, mx, o));
    if ((tid & 31) == 0) sred[tid >> 5] = mx;
    __syncthreads();
    if (tid < 32) {
        float v = (tid < 8) ? sred[tid] : -1e30f;
        #pragma unroll
        for (int o = 4; o > 0; o >>= 1) v = fmaxf(v, __shfl_xor_sync(0xffffffffu, v, o));
        if (tid == 0) sred[0] = v;
    }
    __syncthreads();
    mx = sred[0];
    __syncthreads();

    float s = 0.f;
    #pragma unroll
    for (int k = 0; k < 4; k++) s += __expf(zv[k] - mx);
    #pragma unroll
    for (int o = 16; o > 0; o >>= 1) s += __shfl_xor_sync(0xffffffffu, s, o);
    if ((tid & 31) == 0) sred[tid >> 5] = s;
    __syncthreads();
    if (tid < 32) {
        float v = (tid < 8) ? sred[tid] : 0.f;
        #pragma unroll
        for (int o = 4; o > 0; o >>= 1) v += __shfl_xor_sync(0xffffffffu, v, o);
        if (tid == 0) { g_mx[row] = mx; g_si[row] = 1.f / v; }
    }
}

// ------------------------------------------------------------------
// Kernel 2b: emit P tiles: bf16 hi/lo [i][j] + f32 attention output [j][i]
// ------------------------------------------------------------------
__global__ __launch_bounds__(256) void emit_kernel(
    const float* __restrict__ adj, float* __restrict__ outAtt)
{
    __shared__ float pt[32][33];
    int b  = blockIdx.z;
    int i0 = blockIdx.y * 32;
    int j0 = blockIdx.x * 32;
    int tid = threadIdx.x;
    int ii = tid >> 3, jt = tid & 7;

    const float* fb = g_f + b * NN;
    int irow = (b << 10) + i0 + ii;
    float fi = fb[i0 + ii];
    float mx = g_mx[irow];
    float si = g_si[irow];

    float4 av = *(const float4*)&adj[((size_t)irow) * NN + j0 + jt * 4];
    float p[4];
    #pragma unroll
    for (int e = 0; e < 4; e++) {
        int j = j0 + jt * 4 + e;
        float lg = fi + fb[j];
        float z = (lg >= 0.f ? lg : 0.2f * lg) + ((const float*)&av)[e];
        p[e] = __expf(z - mx) * si;
        pt[ii][jt * 4 + e] = p[e];
    }
    size_t rb = ((size_t)irow) * NN + j0 + jt * 4;
    uint2 hv, lv;
    __nv_bfloat16 h0 = __float2bfloat16(p[0]), h1 = __float2bfloat16(p[1]);
    __nv_bfloat16 h2 = __float2bfloat16(p[2]), h3 = __float2bfloat16(p[3]);
    hv.x = ((uint32_t)*(uint16_t*)&h1 << 16) | *(uint16_t*)&h0;
    hv.y = ((uint32_t)*(uint16_t*)&h3 << 16) | *(uint16_t*)&h2;
    __nv_bfloat16 l0 = __float2bfloat16(p[0] - __bfloat162float(h0));
    __nv_bfloat16 l1 = __float2bfloat16(p[1] - __bfloat162float(h1));
    __nv_bfloat16 l2 = __float2bfloat16(p[2] - __bfloat162float(h2));
    __nv_bfloat16 l3 = __float2bfloat16(p[3] - __bfloat162float(h3));
    lv.x = ((uint32_t)*(uint16_t*)&l1 << 16) | *(uint16_t*)&l0;
    lv.y = ((uint32_t)*(uint16_t*)&l3 << 16) | *(uint16_t*)&l2;
    *(uint2*)&g_Ahi[rb] = hv;
    *(uint2*)&g_Alo[rb] = lv;

    __syncthreads();
    int jj = tid >> 3, it = tid & 7;
    float4 ov;
    ov.x = pt[it * 4 + 0][jj];
    ov.y = pt[it * 4 + 1][jj];
    ov.z = pt[it * 4 + 2][jj];
    ov.w = pt[it * 4 + 3][jj];
    *(float4*)&outAtt[(((size_t)(b << 10) + j0 + jj)) * NN + i0 + it * 4] = ov;
}

// ------------------------------------------------------------------
// Kernel 3: HMMA (mma.sync bf16) 3-term split GEMM, 2 CTAs/SM
// single sync per chunk; cp.async issue moved off the critical path
// ------------------------------------------------------------------
#define STAGE_BYTES (32 * 1024)
#define XT_OFF      (16 * 1024)
#define NCHUNK      32

__device__ __forceinline__ void issue_stage(uint32_t sb,
    const __nv_bfloat16* Ah, const __nv_bfloat16* Al,
    const __nv_bfloat16* Xh, const __nv_bfloat16* Xl,
    int k0, int tid)
{
    int cm = tid >> 3;
    int cu = tid & 7;
    bool isHi = cu < 4;
    int kc = (isHi ? cu : cu - 4) * 8;
    #pragma unroll
    for (int r = 0; r < 4; r++) {
        int m = cm + 32 * r;
        uint32_t sw = (uint32_t)((cu ^ (m & 7)) << 4);
        const __nv_bfloat16* srcA = (isHi ? Ah : Al) + (size_t)m * NN + k0 + kc;
        const __nv_bfloat16* srcX = (isHi ? Xh : Xl) + (size_t)m * NN + k0 + kc;
        cp16(sb + m * 128 + sw, srcA);
        cp16(sb + XT_OFF + m * 128 + sw, srcX);
    }
}

__global__ __launch_bounds__(256, 2) void gemm_hmma_kernel(float* __restrict__ out)
{
    extern __shared__ char smc[];
    int tid  = threadIdx.x;
    int lane = tid & 31, w = tid >> 5;
    int b  = blockIdx.z;
    int n0 = blockIdx.x * 128;
    int m0 = blockIdx.y * 128;

    const __nv_bfloat16* Ah = g_Ahi + ((size_t)(b * NN + m0)) * NN;
    const __nv_bfloat16* Al = g_Alo + ((size_t)(b * NN + m0)) * NN;
    const __nv_bfloat16* Xh = g_Xhi + ((size_t)(b * CL + n0)) * NN;
    const __nv_bfloat16* Xl = g_Xlo + ((size_t)(b * CL + n0)) * NN;

    uint32_t smb = smem_u32(smc);

    issue_stage(smb, Ah, Al, Xh, Xl, 0, tid);
    cp_commit();
    issue_stage(smb + STAGE_BYTES, Ah, Al, Xh, Xl, 32, tid);
    cp_commit();

    int wm = (w & 3) * 32;
    int wn = (w >> 2) * 64;

    float acc[2][8][4];
    #pragma unroll
    for (int t = 0; t < 2; t++)
        #pragma unroll
        for (int bk = 0; bk < 8; bk++)
            #pragma unroll
            for (int e = 0; e < 4; e++) acc[t][bk][e] = 0.f;

    int ai  = lane & 15, ahf = lane >> 4;
    int xcb = (lane >> 4) & 1, xkh = (lane >> 3) & 1, xc7 = lane & 7;

    for (int t = 0; t < NCHUNK; t++) {
        cp_wait1();
        __syncthreads();

        uint32_t sa = smb + (t % 3) * STAGE_BYTES;
        uint32_t sx = sa + XT_OFF;

        #pragma unroll
        for (int s = 0; s < 2; s++) {
            uint32_t ah[2][4], al[2][4];
            #pragma unroll
            for (int mt = 0; mt < 2; mt++) {
                int row = wm + mt * 16 + ai;
                int cuH = 2 * s + ahf;
                ldsm4(ah[mt], sa + row * 128 + ((cuH ^ (row & 7)) << 4));
                ldsm4(al[mt], sa + row * 128 + (((cuH + 4) ^ (row & 7)) << 4));
            }
            #pragma unroll
            for (int g = 0; g < 4; g++) {
                uint32_t xh[4], xl[4];
                int col = wn + g * 16 + xcb * 8 + xc7;
                int cuH = 2 * s + xkh;
                ldsm4(xh, sx + col * 128 + ((cuH ^ (col & 7)) << 4));
                ldsm4(xl, sx + col * 128 + (((cuH + 4) ^ (col & 7)) << 4));
                // term-ordered issue: same-acc reuse distance = 4
                #pragma unroll
                for (int mt = 0; mt < 2; mt++) {
                    mma16816(acc[mt][2 * g],     ah[mt], &xh[0]);
                    mma16816(acc[mt][2 * g + 1], ah[mt], &xh[2]);
                }
                #pragma unroll
                for (int mt = 0; mt < 2; mt++) {
                    mma16816(acc[mt][2 * g],     al[mt], &xh[0]);
                    mma16816(acc[mt][2 * g + 1], al[mt], &xh[2]);
                }
                #pragma unroll
                for (int mt = 0; mt < 2; mt++) {
                    mma16816(acc[mt][2 * g],     ah[mt], &xl[0]);
                    mma16816(acc[mt][2 * g + 1], ah[mt], &xl[2]);
                }
            }
            // issue next stage AFTER the s=0 MMA burst (off the critical path)
            if (s == 0) {
                if (t + 2 < NCHUNK)
                    issue_stage(smb + ((t + 2) % 3) * STAGE_BYTES, Ah, Al, Xh, Xl, (t + 2) * 32, tid);
                cp_commit();
            }
        }
        // no trailing sync: next iteration's top sync orders buffer reuse
    }

    float* ob = out + (size_t)b * COUT * NN * LL;
    int g8 = lane >> 2, t4 = lane & 3;
    #pragma unroll
    for (int mt = 0; mt < 2; mt++) {
        int q0 = m0 + wm + mt * 16 + g8;
        #pragma unroll
        for (int bk = 0; bk < 8; bk++) {
            int cl0 = n0 + wn + bk * 8 + t4 * 2;
            #pragma unroll
            for (int e = 0; e < 4; e++) {
                int q  = q0 + (e >> 1) * 8;
                int cl = cl0 + (e & 1);
                int c = cl / 12, l = cl - c * 12;
                ob[(size_t)c * (NN * LL) + q * 12 + l] = acc[mt][bk][e];
            }
        }
    }
}

// ------------------------------------------------------------------
extern "C" void kernel_launch(void* const* d_in, const int* in_sizes, int n_in,
                              void* d_out, int out_size)
{
    const float* in  = (const float*)d_in[0];
    const float* adj = (const float*)d_in[1];
    const float* w0  = (const float*)d_in[2];
    const float* b0  = (const float*)d_in[3];
    const float* w1  = (const float*)d_in[4];

    float* out    = (float*)d_out;
    float* hprime = out;
    float* att    = out + (size_t)BB * COUT * NN * LL;

    int convSmem = (192 * WPITCH + NT * PPITCH + 256) * (int)sizeof(float);
    cudaFuncSetAttribute(conv_kernel, cudaFuncAttributeMaxDynamicSharedMemorySize, convSmem);
    cudaFuncSetAttribute(gemm_hmma_kernel, cudaFuncAttributeMaxDynamicSharedMemorySize, 3 * STAGE_BYTES);

    conv_kernel<<<BB * (NN / NT), 256, convSmem>>>(in, w0, b0, w1);
    stats_kernel<<<BB * NN, 256>>>(adj);
    emit_kernel<<<dim3(NN / 32, NN / 32, BB), 256>>>(adj, att);
    gemm_hmma_kernel<<<dim3(CL / 128, NN / 128, BB), 256, 3 * STAGE_BYTES>>>(hprime);
}

// round 12
// speedup vs baseline: 1.0993x; 1.0885x over previous
#include <cuda_runtime.h>
#include <cuda_fp16.h>
#include <cstdint>

#define BB   16
#define CIN  64
#define COUT 64
#define NN   1024
#define LL   12
#define CL   768   // COUT*LL

// ------------------- device scratch (allocation-free) -------------------
__device__ float g_f  [(size_t)BB * NN];
__device__ float g_mx [(size_t)BB * NN];
__device__ float g_si [(size_t)BB * NN];
__device__ __half g_Ahi[(size_t)BB * NN * NN];   // [b][q][n]   (GEMM A hi, K-contig)
__device__ __half g_Alo[(size_t)BB * NN * NN];   // A lo (fp16 residual)
__device__ __half g_Xh [(size_t)BB * CL * NN];   // [b][cl][n]  (GEMM B^T, single fp16)

// ------------------- PTX helpers -------------------
__device__ __forceinline__ uint32_t smem_u32(const void* p) {
    uint32_t a;
    asm("{ .reg .u64 t; cvta.to.shared.u64 t, %1; cvt.u32.u64 %0, t; }" : "=r"(a) : "l"(p));
    return a;
}
__device__ __forceinline__ void cp16(uint32_t dst, const void* src) {
    asm volatile("cp.async.cg.shared.global [%0], [%1], 16;" :: "r"(dst), "l"(src));
}
__device__ __forceinline__ void cp_commit() {
    asm volatile("cp.async.commit_group;" ::: "memory");
}
__device__ __forceinline__ void cp_wait1() {
    asm volatile("cp.async.wait_group 1;" ::: "memory");
}
__device__ __forceinline__ void ldsm4(uint32_t* r, uint32_t addr) {
    asm volatile("ldmatrix.sync.aligned.m8n8.x4.shared.b16 {%0,%1,%2,%3}, [%4];"
                 : "=r"(r[0]), "=r"(r[1]), "=r"(r[2]), "=r"(r[3]) : "r"(addr));
}
__device__ __forceinline__ void mma16816(float* d, const uint32_t* a, const uint32_t* bf) {
    asm volatile(
        "mma.sync.aligned.m16n8k16.row.col.f32.f16.f16.f32 "
        "{%0,%1,%2,%3}, {%4,%5,%6,%7}, {%8,%9}, {%0,%1,%2,%3};"
        : "+f"(d[0]), "+f"(d[1]), "+f"(d[2]), "+f"(d[3])
        : "r"(a[0]), "r"(a[1]), "r"(a[2]), "r"(a[3]), "r"(bf[0]), "r"(bf[1]));
}
// packed f32x2 (sm_100+): FFMA2
__device__ __forceinline__ unsigned long long pk2(float a, float b) {
    unsigned long long r;
    asm("mov.b64 %0, {%1, %2};" : "=l"(r) : "f"(a), "f"(b));
    return r;
}
__device__ __forceinline__ void fma2(unsigned long long& d, unsigned long long a, unsigned long long b) {
    asm("fma.rn.f32x2 %0, %1, %2, %0;" : "+l"(d) : "l"(a), "l"(b));
}
__device__ __forceinline__ void upk2(float& x, float& y, unsigned long long v) {
    asm("mov.b64 {%0, %1}, %2;" : "=f"(x), "=f"(y) : "l"(v));
}

// ------------------------------------------------------------------
// Kernel 1: conv0 (1x3, pad 1 on L) + bias; writes fp16 X^T and f
// ------------------------------------------------------------------
#define NT 16
#define WPITCH 68    // 16B-aligned rows -> float4 weight reads
#define PPITCH 898   // 8B-aligned rows  -> float2 patch reads

__global__ __launch_bounds__(256) void conv_kernel(
    const float* __restrict__ in, const float* __restrict__ w0,
    const float* __restrict__ b0, const float* __restrict__ w1)
{
    extern __shared__ float sm[];
    float* Wsh = sm;
    float* Psh = sm + 192 * WPITCH;
    float* red = Psh + NT * PPITCH;

    int blk = blockIdx.x;
    int b   = blk >> 6;
    int n0  = (blk & 63) * NT;
    int tid = threadIdx.x;

    for (int idx = tid; idx < COUT * 192; idx += 256) {
        int cout = idx / 192, r = idx % 192;
        Wsh[r * WPITCH + cout] = w0[idx];
    }
    for (int idx = tid; idx < NT * CIN * 2; idx += 256) {
        int nt = idx >> 7; int r = idx & 127; int cin = r >> 1; int side = r & 1;
        Psh[nt * PPITCH + cin * 14 + side * 13] = 0.f;
    }
    const float* inb = in + (size_t)b * CIN * NN * LL;
    for (int idx = tid; idx < NT * CIN * LL; idx += 256) {
        int cin = idx / (NT * LL); int r = idx % (NT * LL);
        int nt = r / LL; int l = r % LL;
        Psh[nt * PPITCH + cin * 14 + l + 1] = inb[((size_t)cin * NN + n0 + nt) * LL + l];
    }
    __syncthreads();

    int cg = tid >> 4, nt = tid & 15;
    unsigned long long acc2[4][6];
    #pragma unroll
    for (int u = 0; u < 4; u++) {
        float bv = b0[cg * 4 + u];
        unsigned long long bb = pk2(bv, bv);
        #pragma unroll
        for (int j = 0; j < 6; j++) acc2[u][j] = bb;
    }
    const float2* prow2 = (const float2*)(Psh + nt * PPITCH);
    for (int cin = 0; cin < CIN; cin++) {
        unsigned long long P0[7];
        float pv[14];
        #pragma unroll
        for (int j = 0; j < 7; j++) {
            float2 v = prow2[cin * 7 + j];
            pv[2 * j] = v.x; pv[2 * j + 1] = v.y;
            P0[j] = pk2(v.x, v.y);
        }
        unsigned long long P1[6];
        #pragma unroll
        for (int j = 0; j < 6; j++) P1[j] = pk2(pv[2 * j + 1], pv[2 * j + 2]);
        #pragma unroll
        for (int kt = 0; kt < 3; kt++) {
            float4 wv4 = *(const float4*)&Wsh[(cin * 3 + kt) * WPITCH + cg * 4];
            const float* wv = (const float*)&wv4;
            #pragma unroll
            for (int u = 0; u < 4; u++) {
                unsigned long long wv2 = pk2(wv[u], wv[u]);
                #pragma unroll
                for (int j = 0; j < 6; j++) {
                    unsigned long long pvp = (kt == 0) ? P0[j] : (kt == 1 ? P1[j] : P0[j + 1]);
                    fma2(acc2[u][j], wv2, pvp);
                }
            }
        }
    }
    float acc[4][12];
    #pragma unroll
    for (int u = 0; u < 4; u++)
        #pragma unroll
        for (int j = 0; j < 6; j++) upk2(acc[u][2 * j], acc[u][2 * j + 1], acc2[u][j]);

    size_t xbase = (size_t)b * CL * NN;
    float fp = 0.f;
    #pragma unroll
    for (int u = 0; u < 4; u++) {
        int c = cg * 4 + u;
        #pragma unroll
        for (int l = 0; l < 12; l++) {
            float v = acc[u][l];
            int cl = c * 12 + l;
            g_Xh[xbase + (size_t)cl * NN + n0 + nt] = __float2half(v);
            fp += v * __ldg(&w1[cl]);
        }
    }
    red[nt * 16 + cg] = fp;
    __syncthreads();
    if (cg == 0) {
        float s = 0.f;
        #pragma unroll
        for (int k = 0; k < 16; k++) s += red[nt * 16 + k];
        g_f[b * NN + n0 + nt] = s;
    }
}

// ------------------------------------------------------------------
// Kernel 2a: row stats (max, inverse sum) of z = leaky(f_i+f_j)+adj
// ------------------------------------------------------------------
__global__ __launch_bounds__(256) void stats_kernel(const float* __restrict__ adj)
{
    int row = blockIdx.x;
    int b = row >> 10;
    int tid = threadIdx.x;
    const float* arow = adj + (size_t)row * NN;
    const float* fb = g_f + b * NN;
    float fi = fb[row & 1023];

    float zv[4]; float mx = -1e30f;
    #pragma unroll
    for (int k = 0; k < 4; k++) {
        int j = tid + k * 256;
        float lg = fi + fb[j];
        float z = (lg >= 0.f ? lg : 0.2f * lg) + arow[j];
        zv[k] = z; mx = fmaxf(mx, z);
    }
    __shared__ float sred[32];
    #pragma unroll
    for (int o = 16; o > 0; o >>= 1) mx = fmaxf(mx, __shfl_xor_sync(0xffffffffu, mx, o));
    if ((tid & 31) == 0) sred[tid >> 5] = mx;
    __syncthreads();
    if (tid < 32) {
        float v = (tid < 8) ? sred[tid] : -1e30f;
        #pragma unroll
        for (int o = 4; o > 0; o >>= 1) v = fmaxf(v, __shfl_xor_sync(0xffffffffu, v, o));
        if (tid == 0) sred[0] = v;
    }
    __syncthreads();
    mx = sred[0];
    __syncthreads();

    float s = 0.f;
    #pragma unroll
    for (int k = 0; k < 4; k++) s += __expf(zv[k] - mx);
    #pragma unroll
    for (int o = 16; o > 0; o >>= 1) s += __shfl_xor_sync(0xffffffffu, s, o);
    if ((tid & 31) == 0) sred[tid >> 5] = s;
    __syncthreads();
    if (tid < 32) {
        float v = (tid < 8) ? sred[tid] : 0.f;
        #pragma unroll
        for (int o = 4; o > 0; o >>= 1) v += __shfl_xor_sync(0xffffffffu, v, o);
        if (tid == 0) { g_mx[row] = mx; g_si[row] = 1.f / v; }
    }
}

// ------------------------------------------------------------------
// Kernel 2b: emit P tiles: fp16 hi/lo [i][j] + f32 attention output [j][i]
// ------------------------------------------------------------------
__global__ __launch_bounds__(256) void emit_kernel(
    const float* __restrict__ adj, float* __restrict__ outAtt)
{
    __shared__ float pt[32][33];
    int b  = blockIdx.z;
    int i0 = blockIdx.y * 32;
    int j0 = blockIdx.x * 32;
    int tid = threadIdx.x;
    int ii = tid >> 3, jt = tid & 7;

    const float* fb = g_f + b * NN;
    int irow = (b << 10) + i0 + ii;
    float fi = fb[i0 + ii];
    float mx = g_mx[irow];
    float si = g_si[irow];

    float4 av = *(const float4*)&adj[((size_t)irow) * NN + j0 + jt * 4];
    float p[4];
    #pragma unroll
    for (int e = 0; e < 4; e++) {
        int j = j0 + jt * 4 + e;
        float lg = fi + fb[j];
        float z = (lg >= 0.f ? lg : 0.2f * lg) + ((const float*)&av)[e];
        p[e] = __expf(z - mx) * si;
        pt[ii][jt * 4 + e] = p[e];
    }
    size_t rb = ((size_t)irow) * NN + j0 + jt * 4;
    uint2 hv, lv;
    __half h0 = __float2half(p[0]), h1 = __float2half(p[1]);
    __half h2 = __float2half(p[2]), h3 = __float2half(p[3]);
    hv.x = ((uint32_t)*(uint16_t*)&h1 << 16) | *(uint16_t*)&h0;
    hv.y = ((uint32_t)*(uint16_t*)&h3 << 16) | *(uint16_t*)&h2;
    __half l0 = __float2half(p[0] - __half2float(h0));
    __half l1 = __float2half(p[1] - __half2float(h1));
    __half l2 = __float2half(p[2] - __half2float(h2));
    __half l3 = __float2half(p[3] - __half2float(h3));
    lv.x = ((uint32_t)*(uint16_t*)&l1 << 16) | *(uint16_t*)&l0;
    lv.y = ((uint32_t)*(uint16_t*)&l3 << 16) | *(uint16_t*)&l2;
    *(uint2*)&g_Ahi[rb] = hv;
    *(uint2*)&g_Alo[rb] = lv;

    __syncthreads();
    int jj = tid >> 3, it = tid & 7;
    float4 ov;
    ov.x = pt[it * 4 + 0][jj];
    ov.y = pt[it * 4 + 1][jj];
    ov.z = pt[it * 4 + 2][jj];
    ov.w = pt[it * 4 + 3][jj];
    *(float4*)&outAtt[(((size_t)(b << 10) + j0 + jj)) * NN + i0 + it * 4] = ov;
}

// ------------------------------------------------------------------
// Kernel 3: HMMA fp16 2-term split GEMM, 2 CTAs/SM
// C[q][cl] = sum_n (Ahi+Alo)[q][n] * X[n][cl]
// A rows: [hi k0..31 | lo k0..31]; X rows: 128B, hi units only
// ------------------------------------------------------------------
#define STAGE_BYTES (32 * 1024)
#define XT_OFF      (16 * 1024)
#define NCHUNK      32

__device__ __forceinline__ void issue_stage(uint32_t sb,
    const __half* Ah, const __half* Al, const __half* Xh,
    int k0, int tid)
{
    int cm = tid >> 3;
    int cu = tid & 7;
    bool isHi = cu < 4;
    int kc = (isHi ? cu : cu - 4) * 8;
    #pragma unroll
    for (int r = 0; r < 4; r++) {
        int m = cm + 32 * r;
        uint32_t sw = (uint32_t)((cu ^ (m & 7)) << 4);
        const __half* srcA = (isHi ? Ah : Al) + (size_t)m * NN + k0 + kc;
        cp16(sb + m * 128 + sw, srcA);
        if (isHi)   // X: single fp16, hi units only
            cp16(sb + XT_OFF + m * 128 + sw, Xh + (size_t)m * NN + k0 + kc);
    }
}

__global__ __launch_bounds__(256, 2) void gemm_hmma_kernel(float* __restrict__ out)
{
    extern __shared__ char smc[];
    int tid  = threadIdx.x;
    int lane = tid & 31, w = tid >> 5;
    int b  = blockIdx.z;
    int n0 = blockIdx.x * 128;
    int m0 = blockIdx.y * 128;

    const __half* Ah = g_Ahi + ((size_t)(b * NN + m0)) * NN;
    const __half* Al = g_Alo + ((size_t)(b * NN + m0)) * NN;
    const __half* Xh = g_Xh  + ((size_t)(b * CL + n0)) * NN;

    uint32_t smb = smem_u32(smc);

    issue_stage(smb, Ah, Al, Xh, 0, tid);
    cp_commit();
    issue_stage(smb + STAGE_BYTES, Ah, Al, Xh, 32, tid);
    cp_commit();

    int wm = (w & 3) * 32;
    int wn = (w >> 2) * 64;

    float acc[2][8][4];
    #pragma unroll
    for (int t = 0; t < 2; t++)
        #pragma unroll
        for (int bk = 0; bk < 8; bk++)
            #pragma unroll
            for (int e = 0; e < 4; e++) acc[t][bk][e] = 0.f;

    int ai  = lane & 15, ahf = lane >> 4;
    int xcb = (lane >> 4) & 1, xkh = (lane >> 3) & 1, xc7 = lane & 7;

    for (int t = 0; t < NCHUNK; t++) {
        cp_wait1();
        __syncthreads();

        uint32_t sa = smb + (t % 3) * STAGE_BYTES;
        uint32_t sx = sa + XT_OFF;

        #pragma unroll
        for (int s = 0; s < 2; s++) {
            uint32_t ah[2][4], al[2][4];
            #pragma unroll
            for (int mt = 0; mt < 2; mt++) {
                int row = wm + mt * 16 + ai;
                int cuH = 2 * s + ahf;
                ldsm4(ah[mt], sa + row * 128 + ((cuH ^ (row & 7)) << 4));
                ldsm4(al[mt], sa + row * 128 + (((cuH + 4) ^ (row & 7)) << 4));
            }
            #pragma unroll
            for (int g = 0; g < 4; g++) {
                uint32_t xh[4];
                int col = wn + g * 16 + xcb * 8 + xc7;
                int cuH = 2 * s + xkh;
                ldsm4(xh, sx + col * 128 + ((cuH ^ (col & 7)) << 4));
                // 2-term: same-acc reuse distance = 4
                #pragma unroll
                for (int mt = 0; mt < 2; mt++) {
                    mma16816(acc[mt][2 * g],     ah[mt], &xh[0]);
                    mma16816(acc[mt][2 * g + 1], ah[mt], &xh[2]);
                }
                #pragma unroll
                for (int mt = 0; mt < 2; mt++) {
                    mma16816(acc[mt][2 * g],     al[mt], &xh[0]);
                    mma16816(acc[mt][2 * g + 1], al[mt], &xh[2]);
                }
            }
            if (s == 0) {
                if (t + 2 < NCHUNK)
                    issue_stage(smb + ((t + 2) % 3) * STAGE_BYTES, Ah, Al, Xh, (t + 2) * 32, tid);
                cp_commit();
            }
        }
    }

    float* ob = out + (size_t)b * COUT * NN * LL;
    int g8 = lane >> 2, t4 = lane & 3;
    #pragma unroll
    for (int mt = 0; mt < 2; mt++) {
        int q0 = m0 + wm + mt * 16 + g8;
        #pragma unroll
        for (int bk = 0; bk < 8; bk++) {
            int cl0 = n0 + wn + bk * 8 + t4 * 2;
            #pragma unroll
            for (int e = 0; e < 4; e++) {
                int q  = q0 + (e >> 1) * 8;
                int cl = cl0 + (e & 1);
                int c = cl / 12, l = cl - c * 12;
                ob[(size_t)c * (NN * LL) + q * 12 + l] = acc[mt][bk][e];
            }
        }
    }
}

// ------------------------------------------------------------------
extern "C" void kernel_launch(void* const* d_in, const int* in_sizes, int n_in,
                              void* d_out, int out_size)
{
    const float* in  = (const float*)d_in[0];
    const float* adj = (const float*)d_in[1];
    const float* w0  = (const float*)d_in[2];
    const float* b0  = (const float*)d_in[3];
    const float* w1  = (const float*)d_in[4];

    float* out    = (float*)d_out;
    float* hprime = out;
    float* att    = out + (size_t)BB * COUT * NN * LL;

    int convSmem = (192 * WPITCH + NT * PPITCH + 256) * (int)sizeof(float);
    cudaFuncSetAttribute(conv_kernel, cudaFuncAttributeMaxDynamicSharedMemorySize, convSmem);
    cudaFuncSetAttribute(gemm_hmma_kernel, cudaFuncAttributeMaxDynamicSharedMemorySize, 3 * STAGE_BYTES);

    conv_kernel<<<BB * (NN / NT), 256, convSmem>>>(in, w0, b0, w1);
    stats_kernel<<<BB * NN, 256>>>(adj);
    emit_kernel<<<dim3(NN / 32, NN / 32, BB), 256>>>(adj, att);
    gemm_hmma_kernel<<<dim3(CL / 128, NN / 128, BB), 256, 3 * STAGE_BYTES>>>(hprime);
}

// round 13
// speedup vs baseline: 1.5329x; 1.3944x over previous
#include <cuda_runtime.h>
#include <cuda_fp16.h>
#include <cstdint>

#define BB   16
#define CIN  64
#define COUT 64
#define NN   1024
#define LL   12
#define CL   768   // COUT*LL

// ------------------- device scratch (allocation-free) -------------------
__device__ float g_f  [(size_t)BB * NN];
__device__ float g_mx [(size_t)BB * NN];
__device__ float g_si [(size_t)BB * NN];
__device__ __half g_Ahi[(size_t)BB * NN * NN];   // [b][q][n]   (GEMM A, fp16, K-contig)
__device__ __half g_Xh [(size_t)BB * CL * NN];   // [b][cl][n]  (GEMM B^T, fp16, K-contig)

// ------------------- PTX helpers -------------------
__device__ __forceinline__ uint32_t smem_u32(const void* p) {
    uint32_t a;
    asm("{ .reg .u64 t; cvta.to.shared.u64 t, %1; cvt.u32.u64 %0, t; }" : "=r"(a) : "l"(p));
    return a;
}
__device__ __forceinline__ void cp16(uint32_t dst, const void* src) {
    asm volatile("cp.async.cg.shared.global [%0], [%1], 16;" :: "r"(dst), "l"(src));
}
__device__ __forceinline__ void cp_commit() {
    asm volatile("cp.async.commit_group;" ::: "memory");
}
__device__ __forceinline__ void cp_wait1() {
    asm volatile("cp.async.wait_group 1;" ::: "memory");
}
__device__ __forceinline__ void ldsm4(uint32_t* r, uint32_t addr) {
    asm volatile("ldmatrix.sync.aligned.m8n8.x4.shared.b16 {%0,%1,%2,%3}, [%4];"
                 : "=r"(r[0]), "=r"(r[1]), "=r"(r[2]), "=r"(r[3]) : "r"(addr));
}
__device__ __forceinline__ void mma16816(float* d, const uint32_t* a, const uint32_t* bf) {
    asm volatile(
        "mma.sync.aligned.m16n8k16.row.col.f32.f16.f16.f32 "
        "{%0,%1,%2,%3}, {%4,%5,%6,%7}, {%8,%9}, {%0,%1,%2,%3};"
        : "+f"(d[0]), "+f"(d[1]), "+f"(d[2]), "+f"(d[3])
        : "r"(a[0]), "r"(a[1]), "r"(a[2]), "r"(a[3]), "r"(bf[0]), "r"(bf[1]));
}
// packed f32x2 (sm_100+): FFMA2
__device__ __forceinline__ unsigned long long pk2(float a, float b) {
    unsigned long long r;
    asm("mov.b64 %0, {%1, %2};" : "=l"(r) : "f"(a), "f"(b));
    return r;
}
__device__ __forceinline__ void fma2(unsigned long long& d, unsigned long long a, unsigned long long b) {
    asm("fma.rn.f32x2 %0, %1, %2, %0;" : "+l"(d) : "l"(a), "l"(b));
}
__device__ __forceinline__ void upk2(float& x, float& y, unsigned long long v) {
    asm("mov.b64 {%0, %1}, %2;" : "=f"(x), "=f"(y) : "l"(v));
}

// ------------------------------------------------------------------
// Kernel 1: conv0 (1x3, pad 1 on L) + bias; writes fp16 X^T and f
// ------------------------------------------------------------------
#define NT 16
#define WPITCH 68    // 16B-aligned rows -> float4 weight reads
#define PPITCH 898   // 8B-aligned rows  -> float2 patch reads

__global__ __launch_bounds__(256) void conv_kernel(
    const float* __restrict__ in, const float* __restrict__ w0,
    const float* __restrict__ b0, const float* __restrict__ w1)
{
    extern __shared__ float sm[];
    float* Wsh = sm;
    float* Psh = sm + 192 * WPITCH;
    float* red = Psh + NT * PPITCH;

    int blk = blockIdx.x;
    int b   = blk >> 6;
    int n0  = (blk & 63) * NT;
    int tid = threadIdx.x;

    for (int idx = tid; idx < COUT * 192; idx += 256) {
        int cout = idx / 192, r = idx % 192;
        Wsh[r * WPITCH + cout] = w0[idx];
    }
    for (int idx = tid; idx < NT * CIN * 2; idx += 256) {
        int nt = idx >> 7; int r = idx & 127; int cin = r >> 1; int side = r & 1;
        Psh[nt * PPITCH + cin * 14 + side * 13] = 0.f;
    }
    const float* inb = in + (size_t)b * CIN * NN * LL;
    for (int idx = tid; idx < NT * CIN * LL; idx += 256) {
        int cin = idx / (NT * LL); int r = idx % (NT * LL);
        int nt = r / LL; int l = r % LL;
        Psh[nt * PPITCH + cin * 14 + l + 1] = inb[((size_t)cin * NN + n0 + nt) * LL + l];
    }
    __syncthreads();

    int cg = tid >> 4, nt = tid & 15;
    unsigned long long acc2[4][6];
    #pragma unroll
    for (int u = 0; u < 4; u++) {
        float bv = b0[cg * 4 + u];
        unsigned long long bb = pk2(bv, bv);
        #pragma unroll
        for (int j = 0; j < 6; j++) acc2[u][j] = bb;
    }
    const float2* prow2 = (const float2*)(Psh + nt * PPITCH);
    for (int cin = 0; cin < CIN; cin++) {
        unsigned long long P0[7];
        float pv[14];
        #pragma unroll
        for (int j = 0; j < 7; j++) {
            float2 v = prow2[cin * 7 + j];
            pv[2 * j] = v.x; pv[2 * j + 1] = v.y;
            P0[j] = pk2(v.x, v.y);
        }
        unsigned long long P1[6];
        #pragma unroll
        for (int j = 0; j < 6; j++) P1[j] = pk2(pv[2 * j + 1], pv[2 * j + 2]);
        #pragma unroll
        for (int kt = 0; kt < 3; kt++) {
            float4 wv4 = *(const float4*)&Wsh[(cin * 3 + kt) * WPITCH + cg * 4];
            const float* wv = (const float*)&wv4;
            #pragma unroll
            for (int u = 0; u < 4; u++) {
                unsigned long long wv2 = pk2(wv[u], wv[u]);
                #pragma unroll
                for (int j = 0; j < 6; j++) {
                    unsigned long long pvp = (kt == 0) ? P0[j] : (kt == 1 ? P1[j] : P0[j + 1]);
                    fma2(acc2[u][j], wv2, pvp);
                }
            }
        }
    }
    float acc[4][12];
    #pragma unroll
    for (int u = 0; u < 4; u++)
        #pragma unroll
        for (int j = 0; j < 6; j++) upk2(acc[u][2 * j], acc[u][2 * j + 1], acc2[u][j]);

    size_t xbase = (size_t)b * CL * NN;
    float fp = 0.f;
    #pragma unroll
    for (int u = 0; u < 4; u++) {
        int c = cg * 4 + u;
        #pragma unroll
        for (int l = 0; l < 12; l++) {
            float v = acc[u][l];
            int cl = c * 12 + l;
            g_Xh[xbase + (size_t)cl * NN + n0 + nt] = __float2half(v);
            fp += v * __ldg(&w1[cl]);
        }
    }
    red[nt * 16 + cg] = fp;
    __syncthreads();
    if (cg == 0) {
        float s = 0.f;
        #pragma unroll
        for (int k = 0; k < 16; k++) s += red[nt * 16 + k];
        g_f[b * NN + n0 + nt] = s;
    }
}

// ------------------------------------------------------------------
// Kernel 2a: row stats (max, inverse sum) of z = leaky(f_i+f_j)+adj
// ------------------------------------------------------------------
__global__ __launch_bounds__(256) void stats_kernel(const float* __restrict__ adj)
{
    int row = blockIdx.x;
    int b = row >> 10;
    int tid = threadIdx.x;
    const float* arow = adj + (size_t)row * NN;
    const float* fb = g_f + b * NN;
    float fi = fb[row & 1023];

    float zv[4]; float mx = -1e30f;
    #pragma unroll
    for (int k = 0; k < 4; k++) {
        int j = tid + k * 256;
        float lg = fi + fb[j];
        float z = (lg >= 0.f ? lg : 0.2f * lg) + arow[j];
        zv[k] = z; mx = fmaxf(mx, z);
    }
    __shared__ float sred[32];
    #pragma unroll
    for (int o = 16; o > 0; o >>= 1) mx = fmaxf(mx, __shfl_xor_sync(0xffffffffu, mx, o));
    if ((tid & 31) == 0) sred[tid >> 5] = mx;
    __syncthreads();
    if (tid < 32) {
        float v = (tid < 8) ? sred[tid] : -1e30f;
        #pragma unroll
        for (int o = 4; o > 0; o >>= 1) v = fmaxf(v, __shfl_xor_sync(0xffffffffu, v, o));
        if (tid == 0) sred[0] = v;
    }
    __syncthreads();
    mx = sred[0];
    __syncthreads();

    float s = 0.f;
    #pragma unroll
    for (int k = 0; k < 4; k++) s += __expf(zv[k] - mx);
    #pragma unroll
    for (int o = 16; o > 0; o >>= 1) s += __shfl_xor_sync(0xffffffffu, s, o);
    if ((tid & 31) == 0) sred[tid >> 5] = s;
    __syncthreads();
    if (tid < 32) {
        float v = (tid < 8) ? sred[tid] : 0.f;
        #pragma unroll
        for (int o = 4; o > 0; o >>= 1) v += __shfl_xor_sync(0xffffffffu, v, o);
        if (tid == 0) { g_mx[row] = mx; g_si[row] = 1.f / v; }
    }
}

// ------------------------------------------------------------------
// Kernel 2b: emit P tiles: fp16 [i][j] + f32 attention output [j][i]
// ------------------------------------------------------------------
__global__ __launch_bounds__(256) void emit_kernel(
    const float* __restrict__ adj, float* __restrict__ outAtt)
{
    __shared__ float pt[32][33];
    int b  = blockIdx.z;
    int i0 = blockIdx.y * 32;
    int j0 = blockIdx.x * 32;
    int tid = threadIdx.x;
    int ii = tid >> 3, jt = tid & 7;

    const float* fb = g_f + b * NN;
    int irow = (b << 10) + i0 + ii;
    float fi = fb[i0 + ii];
    float mx = g_mx[irow];
    float si = g_si[irow];

    float4 av = *(const float4*)&adj[((size_t)irow) * NN + j0 + jt * 4];
    float p[4];
    #pragma unroll
    for (int e = 0; e < 4; e++) {
        int j = j0 + jt * 4 + e;
        float lg = fi + fb[j];
        float z = (lg >= 0.f ? lg : 0.2f * lg) + ((const float*)&av)[e];
        p[e] = __expf(z - mx) * si;
        pt[ii][jt * 4 + e] = p[e];
    }
    size_t rb = ((size_t)irow) * NN + j0 + jt * 4;
    uint2 hv;
    __half h0 = __float2half(p[0]), h1 = __float2half(p[1]);
    __half h2 = __float2half(p[2]), h3 = __float2half(p[3]);
    hv.x = ((uint32_t)*(uint16_t*)&h1 << 16) | *(uint16_t*)&h0;
    hv.y = ((uint32_t)*(uint16_t*)&h3 << 16) | *(uint16_t*)&h2;
    *(uint2*)&g_Ahi[rb] = hv;

    __syncthreads();
    int jj = tid >> 3, it = tid & 7;
    float4 ov;
    ov.x = pt[it * 4 + 0][jj];
    ov.y = pt[it * 4 + 1][jj];
    ov.z = pt[it * 4 + 2][jj];
    ov.w = pt[it * 4 + 3][jj];
    *(float4*)&outAtt[(((size_t)(b << 10) + j0 + jj)) * NN + i0 + it * 4] = ov;
}

// ------------------------------------------------------------------
// Kernel 3: HMMA fp16 single-term GEMM, 2 CTAs/SM
// C[q][cl] = sum_n A[q][n] * X[n][cl]
// K-chunk 64: rows are 128B = 8 x 16B units spanning k0..k63 (hi only)
// ------------------------------------------------------------------
#define STAGE_BYTES (32 * 1024)
#define XT_OFF      (16 * 1024)
#define NCHUNK      16

__device__ __forceinline__ void issue_stage(uint32_t sb,
    const __half* Ah, const __half* Xh, int k0, int tid)
{
    int cm = tid >> 3;          // base row (0..31)
    int cu = tid & 7;           // 16B unit = k-offset cu*8
    int kc = cu * 8;
    #pragma unroll
    for (int r = 0; r < 4; r++) {
        int m = cm + 32 * r;
        uint32_t sw = (uint32_t)((cu ^ (m & 7)) << 4);
        cp16(sb + m * 128 + sw,          Ah + (size_t)m * NN + k0 + kc);
        cp16(sb + XT_OFF + m * 128 + sw, Xh + (size_t)m * NN + k0 + kc);
    }
}

__global__ __launch_bounds__(256, 2) void gemm_hmma_kernel(float* __restrict__ out)
{
    extern __shared__ char smc[];
    int tid  = threadIdx.x;
    int lane = tid & 31, w = tid >> 5;
    int b  = blockIdx.z;
    int n0 = blockIdx.x * 128;
    int m0 = blockIdx.y * 128;

    const __half* Ah = g_Ahi + ((size_t)(b * NN + m0)) * NN;
    const __half* Xh = g_Xh  + ((size_t)(b * CL + n0)) * NN;

    uint32_t smb = smem_u32(smc);

    issue_stage(smb, Ah, Xh, 0, tid);
    cp_commit();
    issue_stage(smb + STAGE_BYTES, Ah, Xh, 64, tid);
    cp_commit();

    int wm = (w & 3) * 32;
    int wn = (w >> 2) * 64;

    float acc[2][8][4];
    #pragma unroll
    for (int t = 0; t < 2; t++)
        #pragma unroll
        for (int bk = 0; bk < 8; bk++)
            #pragma unroll
            for (int e = 0; e < 4; e++) acc[t][bk][e] = 0.f;

    int ai  = lane & 15, ahf = lane >> 4;
    int xcb = (lane >> 4) & 1, xkh = (lane >> 3) & 1, xc7 = lane & 7;

    for (int t = 0; t < NCHUNK; t++) {
        cp_wait1();
        __syncthreads();

        uint32_t sa = smb + (t % 3) * STAGE_BYTES;
        uint32_t sx = sa + XT_OFF;

        #pragma unroll
        for (int s = 0; s < 4; s++) {        // four k16 steps per 64-chunk
            uint32_t ah[2][4];
            #pragma unroll
            for (int mt = 0; mt < 2; mt++) {
                int row = wm + mt * 16 + ai;
                int cuH = 2 * s + ahf;
                ldsm4(ah[mt], sa + row * 128 + ((cuH ^ (row & 7)) << 4));
            }
            #pragma unroll
            for (int g = 0; g < 4; g++) {
                uint32_t xh[4];
                int col = wn + g * 16 + xcb * 8 + xc7;
                int cuH = 2 * s + xkh;
                ldsm4(xh, sx + col * 128 + ((cuH ^ (col & 7)) << 4));
                #pragma unroll
                for (int mt = 0; mt < 2; mt++) {
                    mma16816(acc[mt][2 * g],     ah[mt], &xh[0]);
                    mma16816(acc[mt][2 * g + 1], ah[mt], &xh[2]);
                }
            }
            if (s == 0) {
                if (t + 2 < NCHUNK)
                    issue_stage(smb + ((t + 2) % 3) * STAGE_BYTES, Ah, Xh, (t + 2) * 64, tid);
                cp_commit();
            }
        }
        // no trailing sync: next iteration's top sync orders buffer reuse
    }

    float* ob = out + (size_t)b * COUT * NN * LL;
    int g8 = lane >> 2, t4 = lane & 3;
    #pragma unroll
    for (int mt = 0; mt < 2; mt++) {
        int q0 = m0 + wm + mt * 16 + g8;
        #pragma unroll
        for (int bk = 0; bk < 8; bk++) {
            int cl0 = n0 + wn + bk * 8 + t4 * 2;
            #pragma unroll
            for (int e = 0; e < 4; e++) {
                int q  = q0 + (e >> 1) * 8;
                int cl = cl0 + (e & 1);
                int c = cl / 12, l = cl - c * 12;
                ob[(size_t)c * (NN * LL) + q * 12 + l] = acc[mt][bk][e];
            }
        }
    }
}

// ------------------------------------------------------------------
extern "C" void kernel_launch(void* const* d_in, const int* in_sizes, int n_in,
                              void* d_out, int out_size)
{
    const float* in  = (const float*)d_in[0];
    const float* adj = (const float*)d_in[1];
    const float* w0  = (const float*)d_in[2];
    const float* b0  = (const float*)d_in[3];
    const float* w1  = (const float*)d_in[4];

    float* out    = (float*)d_out;
    float* hprime = out;
    float* att    = out + (size_t)BB * COUT * NN * LL;

    int convSmem = (192 * WPITCH + NT * PPITCH + 256) * (int)sizeof(float);
    cudaFuncSetAttribute(conv_kernel, cudaFuncAttributeMaxDynamicSharedMemorySize, convSmem);
    cudaFuncSetAttribute(gemm_hmma_kernel, cudaFuncAttributeMaxDynamicSharedMemorySize, 3 * STAGE_BYTES);

    conv_kernel<<<BB * (NN / NT), 256, convSmem>>>(in, w0, b0, w1);
    stats_kernel<<<BB * NN, 256>>>(adj);
    emit_kernel<<<dim3(NN / 32, NN / 32, BB), 256>>>(adj, att);
    gemm_hmma_kernel<<<dim3(CL / 128, NN / 128, BB), 256, 3 * STAGE_BYTES>>>(hprime);
}

// round 14
// speedup vs baseline: 1.7889x; 1.1670x over previous
#include <cuda_runtime.h>
#include <cuda_fp16.h>
#include <cstdint>

#define BB   16
#define CIN  64
#define COUT 64
#define NN   1024
#define LL   12
#define CL   768   // COUT*LL

// ------------------- device scratch (allocation-free) -------------------
__device__ float g_f  [(size_t)BB * NN];
__device__ float g_mx [(size_t)BB * NN];
__device__ float g_si [(size_t)BB * NN];
__device__ float g_weff[CIN * 12];
__device__ float g_fconst;
__device__ __half g_Ahi[(size_t)BB * NN * NN];   // [b][q][n]   (GEMM A, fp16, K-contig)
__device__ __half g_Xh [(size_t)BB * CL * NN];   // [b][cl][n]  (GEMM B^T, fp16, K-contig)

// ------------------- PTX helpers -------------------
__device__ __forceinline__ uint32_t smem_u32(const void* p) {
    uint32_t a;
    asm("{ .reg .u64 t; cvta.to.shared.u64 t, %1; cvt.u32.u64 %0, t; }" : "=r"(a) : "l"(p));
    return a;
}
__device__ __forceinline__ void cp16(uint32_t dst, const void* src) {
    asm volatile("cp.async.cg.shared.global [%0], [%1], 16;" :: "r"(dst), "l"(src));
}
__device__ __forceinline__ void cp_commit() {
    asm volatile("cp.async.commit_group;" ::: "memory");
}
__device__ __forceinline__ void cp_wait1() {
    asm volatile("cp.async.wait_group 1;" ::: "memory");
}
__device__ __forceinline__ void ldsm4(uint32_t* r, uint32_t addr) {
    asm volatile("ldmatrix.sync.aligned.m8n8.x4.shared.b16 {%0,%1,%2,%3}, [%4];"
                 : "=r"(r[0]), "=r"(r[1]), "=r"(r[2]), "=r"(r[3]) : "r"(addr));
}
__device__ __forceinline__ void mma16816(float* d, const uint32_t* a, const uint32_t* bf) {
    asm volatile(
        "mma.sync.aligned.m16n8k16.row.col.f32.f16.f16.f32 "
        "{%0,%1,%2,%3}, {%4,%5,%6,%7}, {%8,%9}, {%0,%1,%2,%3};"
        : "+f"(d[0]), "+f"(d[1]), "+f"(d[2]), "+f"(d[3])
        : "r"(a[0]), "r"(a[1]), "r"(a[2]), "r"(a[3]), "r"(bf[0]), "r"(bf[1]));
}

// ------------------------------------------------------------------
// Kernel 0: effective f-weights: f[b,n] = fconst + <in[b,:,n,:], weff>
// ------------------------------------------------------------------
__global__ void weff_kernel(const float* __restrict__ w0,
                            const float* __restrict__ b0,
                            const float* __restrict__ w1)
{
    int t = threadIdx.x;              // 768 = cin*12 + lp
    int cin = t / 12, lp = t % 12;
    float s = 0.f;
    for (int c = 0; c < COUT; c++) {
        #pragma unroll
        for (int kt = 0; kt < 3; kt++) {
            int l = lp - kt + 1;
            if (l >= 0 && l < 12)
                s += w0[c * 192 + cin * 3 + kt] * w1[c * 12 + l];
        }
    }
    g_weff[t] = s;
    if (t == 0) {
        float fc = 0.f;
        for (int c = 0; c < COUT; c++) {
            float sw = 0.f;
            for (int l = 0; l < 12; l++) sw += w1[c * 12 + l];
            fc += b0[c] * sw;
        }
        g_fconst = fc;
    }
}

// ------------------------------------------------------------------
// Kernel 1: conv as HMMA im2col GEMM (M=64 cout, K=192, 96 (n,l) cols/CTA)
// fp16 operands, fp32 accum; f computed fp32 from inputs via weff.
// smem rows 400B pitch (conflict-free ldmatrix, no swizzle).
// ------------------------------------------------------------------
#define CPITCH 400
#define B_OFF  (64 * CPITCH)                 // 25600
#define WF_OFF (B_OFF + 96 * CPITCH)         // 64000
#define CSMEM  (WF_OFF + 768 * 4 + 128)      // 67200

__global__ __launch_bounds__(256) void convmma_kernel(
    const float* __restrict__ in, const float* __restrict__ w0,
    const float* __restrict__ b0)
{
    extern __shared__ char cs[];
    uint32_t sb = smem_u32(cs);
    int tid = threadIdx.x;
    int lane = tid & 31, w = tid >> 5;
    int b  = blockIdx.y;
    int n0 = blockIdx.x * 8;

    // phase 1: weights -> A smem (fp16), weff -> smem, zero B
    for (int idx = tid; idx < COUT * 192; idx += 256) {
        int cout = idx / 192, k = idx % 192;
        *(__half*)(cs + cout * CPITCH + k * 2) = __float2half(w0[idx]);
    }
    for (int idx = tid; idx < 768; idx += 256)
        *(float*)(cs + WF_OFF + idx * 4) = g_weff[idx];
    uint4 zz = make_uint4(0, 0, 0, 0);
    for (int idx = tid; idx < 96 * CPITCH / 16; idx += 256)
        *(uint4*)(cs + B_OFF + idx * 16) = zz;
    __syncthreads();

    // phase 2: im2col fill (fp16) + f (fp32)
    {
        int gid = tid >> 5;              // n = n0 + gid
        const float* weffS = (const float*)(cs + WF_OFF);
        float fp = 0.f;
        #pragma unroll
        for (int c2 = 0; c2 < 2; c2++) {
            int cin = lane + 32 * c2;
            const float* src = in + ((size_t)b * CIN + cin) * (NN * LL) + (size_t)(n0 + gid) * LL;
            float4 v0 = *(const float4*)(src);
            float4 v1 = *(const float4*)(src + 4);
            float4 v2 = *(const float4*)(src + 8);
            float v[12] = {v0.x, v0.y, v0.z, v0.w, v1.x, v1.y, v1.z, v1.w,
                           v2.x, v2.y, v2.z, v2.w};
            #pragma unroll
            for (int lp = 0; lp < 12; lp++) {
                fp += v[lp] * weffS[cin * 12 + lp];
                __half h = __float2half(v[lp]);
                // kt=1 -> l=lp
                *(__half*)(cs + B_OFF + (gid * 12 + lp) * CPITCH + (cin * 3 + 1) * 2) = h;
                if (lp <= 10)  // kt=0 -> l=lp+1
                    *(__half*)(cs + B_OFF + (gid * 12 + lp + 1) * CPITCH + (cin * 3 + 0) * 2) = h;
                if (lp >= 1)   // kt=2 -> l=lp-1
                    *(__half*)(cs + B_OFF + (gid * 12 + lp - 1) * CPITCH + (cin * 3 + 2) * 2) = h;
            }
        }
        #pragma unroll
        for (int o = 16; o > 0; o >>= 1) fp += __shfl_xor_sync(0xffffffffu, fp, o);
        if (lane == 0) g_f[b * NN + n0 + gid] = fp + g_fconst;
    }
    __syncthreads();

    // phase 3: MMA — warp tile 16(m) x 48(n), K=192 in 12 k16 steps
    int wm16 = (w & 3) * 16;
    int wn48 = (w >> 2) * 48;
    float acc[6][4];
    #pragma unroll
    for (int bk = 0; bk < 6; bk++)
        #pragma unroll
        for (int e = 0; e < 4; e++) acc[bk][e] = 0.f;

    int ai = lane & 15, ahf = lane >> 4;
    int xcb = (lane >> 4) & 1, xkh = (lane >> 3) & 1, xc7 = lane & 7;

    #pragma unroll
    for (int s = 0; s < 12; s++) {
        uint32_t af[4];
        ldsm4(af, sb + (wm16 + ai) * CPITCH + (2 * s + ahf) * 16);
        #pragma unroll
        for (int g = 0; g < 3; g++) {
            uint32_t xf[4];
            int col = wn48 + g * 16 + xcb * 8 + xc7;
            ldsm4(xf, sb + B_OFF + col * CPITCH + (2 * s + xkh) * 16);
            mma16816(acc[2 * g],     af, &xf[0]);
            mma16816(acc[2 * g + 1], af, &xf[2]);
        }
    }
    __syncthreads();   // all B reads done; reuse B region as stage

    // phase 4: bias + stage (fp16 [64][96], pitch 100 halves)
    __half* stg = (__half*)(cs + B_OFF);
    #pragma unroll
    for (int bk = 0; bk < 6; bk++) {
        #pragma unroll
        for (int e = 0; e < 4; e++) {
            int m   = wm16 + (lane >> 2) + 8 * (e >> 1);
            int col = wn48 + bk * 8 + (lane & 3) * 2 + (e & 1);
            stg[m * 100 + col] = __float2half(acc[bk][e] + __ldg(&b0[m]));
        }
    }
    __syncthreads();

    // phase 5: write X^T: g_Xh[b][cout*12+l][n0..n0+7] (16B rows)
    for (int idx = tid; idx < 768; idx += 256) {
        int cout = idx / 12, l = idx % 12;
        __half tmp[8];
        #pragma unroll
        for (int nl = 0; nl < 8; nl++) tmp[nl] = stg[cout * 100 + nl * 12 + l];
        *(uint4*)&g_Xh[((size_t)b * CL + cout * 12 + l) * NN + n0] = *(uint4*)tmp;
    }
}

// ------------------------------------------------------------------
// Kernel 2a: row stats (max, inverse sum) of z = leaky(f_i+f_j)+adj
// ------------------------------------------------------------------
__global__ __launch_bounds__(256) void stats_kernel(const float* __restrict__ adj)
{
    int row = blockIdx.x;
    int b = row >> 10;
    int tid = threadIdx.x;
    const float* arow = adj + (size_t)row * NN;
    const float* fb = g_f + b * NN;
    float fi = fb[row & 1023];

    float zv[4]; float mx = -1e30f;
    #pragma unroll
    for (int k = 0; k < 4; k++) {
        int j = tid + k * 256;
        float lg = fi + fb[j];
        float z = (lg >= 0.f ? lg : 0.2f * lg) + arow[j];
        zv[k] = z; mx = fmaxf(mx, z);
    }
    __shared__ float sred[32];
    #pragma unroll
    for (int o = 16; o > 0; o >>= 1) mx = fmaxf(mx, __shfl_xor_sync(0xffffffffu, mx, o));
    if ((tid & 31) == 0) sred[tid >> 5] = mx;
    __syncthreads();
    if (tid < 32) {
        float v = (tid < 8) ? sred[tid] : -1e30f;
        #pragma unroll
        for (int o = 4; o > 0; o >>= 1) v = fmaxf(v, __shfl_xor_sync(0xffffffffu, v, o));
        if (tid == 0) sred[0] = v;
    }
    __syncthreads();
    mx = sred[0];
    __syncthreads();

    float s = 0.f;
    #pragma unroll
    for (int k = 0; k < 4; k++) s += __expf(zv[k] - mx);
    #pragma unroll
    for (int o = 16; o > 0; o >>= 1) s += __shfl_xor_sync(0xffffffffu, s, o);
    if ((tid & 31) == 0) sred[tid >> 5] = s;
    __syncthreads();
    if (tid < 32) {
        float v = (tid < 8) ? sred[tid] : 0.f;
        #pragma unroll
        for (int o = 4; o > 0; o >>= 1) v += __shfl_xor_sync(0xffffffffu, v, o);
        if (tid == 0) { g_mx[row] = mx; g_si[row] = 1.f / v; }
    }
}

// ------------------------------------------------------------------
// Kernel 2b: emit P tiles: fp16 [i][j] + f32 attention output [j][i]
// ------------------------------------------------------------------
__global__ __launch_bounds__(256) void emit_kernel(
    const float* __restrict__ adj, float* __restrict__ outAtt)
{
    __shared__ float pt[32][33];
    int b  = blockIdx.z;
    int i0 = blockIdx.y * 32;
    int j0 = blockIdx.x * 32;
    int tid = threadIdx.x;
    int ii = tid >> 3, jt = tid & 7;

    const float* fb = g_f + b * NN;
    int irow = (b << 10) + i0 + ii;
    float fi = fb[i0 + ii];
    float mx = g_mx[irow];
    float si = g_si[irow];

    float4 av = *(const float4*)&adj[((size_t)irow) * NN + j0 + jt * 4];
    float p[4];
    #pragma unroll
    for (int e = 0; e < 4; e++) {
        int j = j0 + jt * 4 + e;
        float lg = fi + fb[j];
        float z = (lg >= 0.f ? lg : 0.2f * lg) + ((const float*)&av)[e];
        p[e] = __expf(z - mx) * si;
        pt[ii][jt * 4 + e] = p[e];
    }
    size_t rb = ((size_t)irow) * NN + j0 + jt * 4;
    uint2 hv;
    __half h0 = __float2half(p[0]), h1 = __float2half(p[1]);
    __half h2 = __float2half(p[2]), h3 = __float2half(p[3]);
    hv.x = ((uint32_t)*(uint16_t*)&h1 << 16) | *(uint16_t*)&h0;
    hv.y = ((uint32_t)*(uint16_t*)&h3 << 16) | *(uint16_t*)&h2;
    *(uint2*)&g_Ahi[rb] = hv;

    __syncthreads();
    int jj = tid >> 3, it = tid & 7;
    float4 ov;
    ov.x = pt[it * 4 + 0][jj];
    ov.y = pt[it * 4 + 1][jj];
    ov.z = pt[it * 4 + 2][jj];
    ov.w = pt[it * 4 + 3][jj];
    *(float4*)&outAtt[(((size_t)(b << 10) + j0 + jj)) * NN + i0 + it * 4] = ov;
}

// ------------------------------------------------------------------
// Kernel 3: HMMA fp16 single-term GEMM, 2 CTAs/SM (unchanged from R13)
// ------------------------------------------------------------------
#define STAGE_BYTES (32 * 1024)
#define XT_OFF      (16 * 1024)
#define NCHUNK      16

__device__ __forceinline__ void issue_stage(uint32_t sb,
    const __half* Ah, const __half* Xh, int k0, int tid)
{
    int cm = tid >> 3;
    int cu = tid & 7;
    int kc = cu * 8;
    #pragma unroll
    for (int r = 0; r < 4; r++) {
        int m = cm + 32 * r;
        uint32_t sw = (uint32_t)((cu ^ (m & 7)) << 4);
        cp16(sb + m * 128 + sw,          Ah + (size_t)m * NN + k0 + kc);
        cp16(sb + XT_OFF + m * 128 + sw, Xh + (size_t)m * NN + k0 + kc);
    }
}

__global__ __launch_bounds__(256, 2) void gemm_hmma_kernel(float* __restrict__ out)
{
    extern __shared__ char smc[];
    int tid  = threadIdx.x;
    int lane = tid & 31, w = tid >> 5;
    int b  = blockIdx.z;
    int n0 = blockIdx.x * 128;
    int m0 = blockIdx.y * 128;

    const __half* Ah = g_Ahi + ((size_t)(b * NN + m0)) * NN;
    const __half* Xh = g_Xh  + ((size_t)(b * CL + n0)) * NN;

    uint32_t smb = smem_u32(smc);

    issue_stage(smb, Ah, Xh, 0, tid);
    cp_commit();
    issue_stage(smb + STAGE_BYTES, Ah, Xh, 64, tid);
    cp_commit();

    int wm = (w & 3) * 32;
    int wn = (w >> 2) * 64;

    float acc[2][8][4];
    #pragma unroll
    for (int t = 0; t < 2; t++)
        #pragma unroll
        for (int bk = 0; bk < 8; bk++)
            #pragma unroll
            for (int e = 0; e < 4; e++) acc[t][bk][e] = 0.f;

    int ai  = lane & 15, ahf = lane >> 4;
    int xcb = (lane >> 4) & 1, xkh = (lane >> 3) & 1, xc7 = lane & 7;

    for (int t = 0; t < NCHUNK; t++) {
        cp_wait1();
        __syncthreads();

        uint32_t sa = smb + (t % 3) * STAGE_BYTES;
        uint32_t sx = sa + XT_OFF;

        #pragma unroll
        for (int s = 0; s < 4; s++) {
            uint32_t ah[2][4];
            #pragma unroll
            for (int mt = 0; mt < 2; mt++) {
                int row = wm + mt * 16 + ai;
                int cuH = 2 * s + ahf;
                ldsm4(ah[mt], sa + row * 128 + ((cuH ^ (row & 7)) << 4));
            }
            #pragma unroll
            for (int g = 0; g < 4; g++) {
                uint32_t xh[4];
                int col = wn + g * 16 + xcb * 8 + xc7;
                int cuH = 2 * s + xkh;
                ldsm4(xh, sx + col * 128 + ((cuH ^ (col & 7)) << 4));
                #pragma unroll
                for (int mt = 0; mt < 2; mt++) {
                    mma16816(acc[mt][2 * g],     ah[mt], &xh[0]);
                    mma16816(acc[mt][2 * g + 1], ah[mt], &xh[2]);
                }
            }
            if (s == 0) {
                if (t + 2 < NCHUNK)
                    issue_stage(smb + ((t + 2) % 3) * STAGE_BYTES, Ah, Xh, (t + 2) * 64, tid);
                cp_commit();
            }
        }
    }

    float* ob = out + (size_t)b * COUT * NN * LL;
    int g8 = lane >> 2, t4 = lane & 3;
    #pragma unroll
    for (int mt = 0; mt < 2; mt++) {
        int q0 = m0 + wm + mt * 16 + g8;
        #pragma unroll
        for (int bk = 0; bk < 8; bk++) {
            int cl0 = n0 + wn + bk * 8 + t4 * 2;
            #pragma unroll
            for (int e = 0; e < 4; e++) {
                int q  = q0 + (e >> 1) * 8;
                int cl = cl0 + (e & 1);
                int c = cl / 12, l = cl - c * 12;
                ob[(size_t)c * (NN * LL) + q * 12 + l] = acc[mt][bk][e];
            }
        }
    }
}

// ------------------------------------------------------------------
extern "C" void kernel_launch(void* const* d_in, const int* in_sizes, int n_in,
                              void* d_out, int out_size)
{
    const float* in  = (const float*)d_in[0];
    const float* adj = (const float*)d_in[1];
    const float* w0  = (const float*)d_in[2];
    const float* b0  = (const float*)d_in[3];
    const float* w1  = (const float*)d_in[4];

    float* out    = (float*)d_out;
    float* hprime = out;
    float* att    = out + (size_t)BB * COUT * NN * LL;

    cudaFuncSetAttribute(convmma_kernel, cudaFuncAttributeMaxDynamicSharedMemorySize, CSMEM);
    cudaFuncSetAttribute(gemm_hmma_kernel, cudaFuncAttributeMaxDynamicSharedMemorySize, 3 * STAGE_BYTES);

    weff_kernel<<<1, 768>>>(w0, b0, w1);
    convmma_kernel<<<dim3(NN / 8, BB), 256, CSMEM>>>(in, w0, b0);
    stats_kernel<<<BB * NN, 256>>>(adj);
    emit_kernel<<<dim3(NN / 32, NN / 32, BB), 256>>>(adj, att);
    gemm_hmma_kernel<<<dim3(CL / 128, NN / 128, BB), 256, 3 * STAGE_BYTES>>>(hprime);
}

// round 16
// speedup vs baseline: 1.8948x; 1.0592x over previous
#include <cuda_runtime.h>
#include <cuda_fp16.h>
#include <cstdint>

#define BB   16
#define CIN  64
#define COUT 64
#define NN   1024
#define LL   12
#define CL   768   // COUT*LL

// ------------------- device scratch (allocation-free) -------------------
__device__ float g_f   [(size_t)BB * NN];
__device__ float g_fmax[BB];
__device__ float g_si  [(size_t)BB * NN];     // 1 / sum(e') per row
__device__ float g_weff[CIN * 12];
__device__ float g_fconst;
__device__ __align__(16) __half g_Wh [(size_t)COUT * 192];
__device__ __align__(16) __half g_Ahi[(size_t)BB * NN * NN];   // [b][q][n] unnormalized e'
__device__ __align__(16) __half g_Xh [(size_t)BB * CL * NN];   // [b][cl][n]

// ------------------- PTX helpers -------------------
__device__ __forceinline__ uint32_t smem_u32(const void* p) {
    uint32_t a;
    asm("{ .reg .u64 t; cvta.to.shared.u64 t, %1; cvt.u32.u64 %0, t; }" : "=r"(a) : "l"(p));
    return a;
}
__device__ __forceinline__ void cp16(uint32_t dst, const void* src) {
    asm volatile("cp.async.cg.shared.global [%0], [%1], 16;" :: "r"(dst), "l"(src));
}
__device__ __forceinline__ void cp_commit() {
    asm volatile("cp.async.commit_group;" ::: "memory");
}
__device__ __forceinline__ void cp_wait1() {
    asm volatile("cp.async.wait_group 1;" ::: "memory");
}
__device__ __forceinline__ void cp_wait0() {
    asm volatile("cp.async.wait_group 0;" ::: "memory");
}
__device__ __forceinline__ void ldsm4(uint32_t* r, uint32_t addr) {
    asm volatile("ldmatrix.sync.aligned.m8n8.x4.shared.b16 {%0,%1,%2,%3}, [%4];"
                 : "=r"(r[0]), "=r"(r[1]), "=r"(r[2]), "=r"(r[3]) : "r"(addr));
}
__device__ __forceinline__ void mma16816(float* d, const uint32_t* a, const uint32_t* bf) {
    asm volatile(
        "mma.sync.aligned.m16n8k16.row.col.f32.f16.f16.f32 "
        "{%0,%1,%2,%3}, {%4,%5,%6,%7}, {%8,%9}, {%0,%1,%2,%3};"
        : "+f"(d[0]), "+f"(d[1]), "+f"(d[2]), "+f"(d[3])
        : "r"(a[0]), "r"(a[1]), "r"(a[2]), "r"(a[3]), "r"(bf[0]), "r"(bf[1]));
}

// ------------------------------------------------------------------
// Kernel 0: effective f-weights + fp16 weight matrix
// ------------------------------------------------------------------
__global__ void weff_kernel(const float* __restrict__ w0,
                            const float* __restrict__ b0,
                            const float* __restrict__ w1)
{
    int t = threadIdx.x;              // 768
    int cin = t / 12, lp = t % 12;
    float s = 0.f;
    for (int c = 0; c < COUT; c++) {
        #pragma unroll
        for (int kt = 0; kt < 3; kt++) {
            int l = lp - kt + 1;
            if (l >= 0 && l < 12)
                s += w0[c * 192 + cin * 3 + kt] * w1[c * 12 + l];
        }
    }
    g_weff[t] = s;
    for (int idx = t; idx < COUT * 192; idx += 768)
        g_Wh[idx] = __float2half(w0[idx]);
    if (t == 0) {
        float fc = 0.f;
        for (int c = 0; c < COUT; c++) {
            float sw = 0.f;
            for (int l = 0; l < 12; l++) sw += w1[c * 12 + l];
            fc += b0[c] * sw;
        }
        g_fconst = fc;
    }
}

// ------------------------------------------------------------------
// Kernel 1: conv as HMMA im2col GEMM; weights via cp.async from g_Wh
// ------------------------------------------------------------------
#define CPITCH 400
#define B_OFF  (64 * CPITCH)
#define WF_OFF (B_OFF + 96 * CPITCH)
#define CSMEM  (WF_OFF + 768 * 4 + 128)

__global__ __launch_bounds__(256) void convmma_kernel(
    const float* __restrict__ in, const float* __restrict__ b0)
{
    extern __shared__ char cs[];
    uint32_t sb = smem_u32(cs);
    int tid = threadIdx.x;
    int lane = tid & 31, w = tid >> 5;
    int b  = blockIdx.y;
    int n0 = blockIdx.x * 8;

    // phase 1a: async weight copy (fp16, 64 rows x 384B)
    for (int idx = tid; idx < 1536; idx += 256) {
        int cout = idx / 24, k = idx % 24;
        cp16(sb + cout * CPITCH + k * 16, &g_Wh[cout * 192 + k * 8]);
    }
    cp_commit();
    // phase 1b: weff to smem + boundary zeros of B
    for (int idx = tid; idx < 768; idx += 256)
        *(float*)(cs + WF_OFF + idx * 4) = g_weff[idx];
    for (int idx = tid; idx < 1024; idx += 256) {
        int gid = idx >> 7; int r = idx & 127; int cin = r >> 1; int side = r & 1;
        int row = gid * 12 + (side ? 11 : 0);
        int col = cin * 3 + (side ? 2 : 0);
        *(__half*)(cs + B_OFF + row * CPITCH + col * 2) = __float2half(0.f);
    }
    __syncthreads();   // weff visible for phase 2

    // phase 2: im2col fill (fp16) + f (fp32)
    {
        int gid = tid >> 5;
        const float* weffS = (const float*)(cs + WF_OFF);
        float fp = 0.f;
        #pragma unroll
        for (int c2 = 0; c2 < 2; c2++) {
            int cin = lane + 32 * c2;
            const float* src = in + ((size_t)b * CIN + cin) * (NN * LL) + (size_t)(n0 + gid) * LL;
            float4 v0 = *(const float4*)(src);
            float4 v1 = *(const float4*)(src + 4);
            float4 v2 = *(const float4*)(src + 8);
            float v[12] = {v0.x, v0.y, v0.z, v0.w, v1.x, v1.y, v1.z, v1.w,
                           v2.x, v2.y, v2.z, v2.w};
            #pragma unroll
            for (int lp = 0; lp < 12; lp++) {
                fp += v[lp] * weffS[cin * 12 + lp];
                __half h = __float2half(v[lp]);
                *(__half*)(cs + B_OFF + (gid * 12 + lp) * CPITCH + (cin * 3 + 1) * 2) = h;
                if (lp <= 10)
                    *(__half*)(cs + B_OFF + (gid * 12 + lp + 1) * CPITCH + (cin * 3 + 0) * 2) = h;
                if (lp >= 1)
                    *(__half*)(cs + B_OFF + (gid * 12 + lp - 1) * CPITCH + (cin * 3 + 2) * 2) = h;
            }
        }
        #pragma unroll
        for (int o = 16; o > 0; o >>= 1) fp += __shfl_xor_sync(0xffffffffu, fp, o);
        if (lane == 0) g_f[b * NN + n0 + gid] = fp + g_fconst;
    }
    cp_wait0();
    __syncthreads();

    // phase 3: MMA — warp tile 16(m) x 48(n), K=192
    int wm16 = (w & 3) * 16;
    int wn48 = (w >> 2) * 48;
    float acc[6][4];
    #pragma unroll
    for (int bk = 0; bk < 6; bk++)
        #pragma unroll
        for (int e = 0; e < 4; e++) acc[bk][e] = 0.f;

    int ai = lane & 15, ahf = lane >> 4;
    int xcb = (lane >> 4) & 1, xkh = (lane >> 3) & 1, xc7 = lane & 7;

    #pragma unroll
    for (int s = 0; s < 12; s++) {
        uint32_t af[4];
        ldsm4(af, sb + (wm16 + ai) * CPITCH + (2 * s + ahf) * 16);
        #pragma unroll
        for (int g = 0; g < 3; g++) {
            uint32_t xf[4];
            int col = wn48 + g * 16 + xcb * 8 + xc7;
            ldsm4(xf, sb + B_OFF + col * CPITCH + (2 * s + xkh) * 16);
            mma16816(acc[2 * g],     af, &xf[0]);
            mma16816(acc[2 * g + 1], af, &xf[2]);
        }
    }
    __syncthreads();

    // phase 4: bias + stage
    __half* stg = (__half*)(cs + B_OFF);
    #pragma unroll
    for (int bk = 0; bk < 6; bk++) {
        #pragma unroll
        for (int e = 0; e < 4; e++) {
            int m   = wm16 + (lane >> 2) + 8 * (e >> 1);
            int col = wn48 + bk * 8 + (lane & 3) * 2 + (e & 1);
            stg[m * 100 + col] = __float2half(acc[bk][e] + __ldg(&b0[m]));
        }
    }
    __syncthreads();

    // phase 5: write X^T
    for (int idx = tid; idx < 768; idx += 256) {
        int cout = idx / 12, l = idx % 12;
        __half tmp[8];
        #pragma unroll
        for (int nl = 0; nl < 8; nl++) tmp[nl] = stg[cout * 100 + nl * 12 + l];
        *(uint4*)&g_Xh[((size_t)b * CL + cout * 12 + l) * NN + n0] = *(uint4*)tmp;
    }
}

// ------------------------------------------------------------------
// Kernel 2: per-batch max of f
// ------------------------------------------------------------------
__global__ __launch_bounds__(256) void fmax_kernel()
{
    int b = blockIdx.x, tid = threadIdx.x;
    const float* fb = g_f + b * NN;
    float m = -1e30f;
    #pragma unroll
    for (int k = 0; k < 4; k++) m = fmaxf(m, fb[tid + k * 256]);
    __shared__ float sred[8];
    #pragma unroll
    for (int o = 16; o > 0; o >>= 1) m = fmaxf(m, __shfl_xor_sync(0xffffffffu, m, o));
    if ((tid & 31) == 0) sred[tid >> 5] = m;
    __syncthreads();
    if (tid == 0) {
        float v = sred[0];
        #pragma unroll
        for (int k = 1; k < 8; k++) v = fmaxf(v, sred[k]);
        g_fmax[b] = v;
    }
}

// ------------------------------------------------------------------
// Kernel 3: fused softmax. Block = 8 full rows (one warp per row).
// e' = exp(z - c), c = f_i + fmax + 1 (valid shift; no max pass).
// Writes: g_Ahi = fp16 e' (unnorm), g_si = 1/sum, att = e'*si transposed f32.
// ------------------------------------------------------------------
#define SMAX_SMEM (1024 * 9 * 4)

__global__ __launch_bounds__(256) void smax_kernel(
    const float* __restrict__ adj, float* __restrict__ outAtt)
{
    extern __shared__ float es[];     // [1024][9] f32 e', pitch 9 (conflict-free)
    __shared__ float s_si[8];
    int b  = blockIdx.y;
    int i0 = blockIdx.x * 8;
    int tid = threadIdx.x;
    int lane = tid & 31, wr = tid >> 5;     // wr = local row

    const float* fb = g_f + b * NN;
    int irow = (b << 10) + i0 + wr;
    float fi = fb[i0 + wr];
    float c  = fi + g_fmax[b] + 1.0f;
    const float* arow = adj + (size_t)irow * NN;

    float sum = 0.f;
    #pragma unroll
    for (int kk = 0; kk < 8; kk++) {
        int j = lane * 4 + kk * 128;
        float4 av = *(const float4*)&arow[j];
        float e[4];
        #pragma unroll
        for (int u = 0; u < 4; u++) {
            float lg = fi + fb[j + u];
            float z  = (lg >= 0.f ? lg : 0.2f * lg) + ((const float*)&av)[u];
            e[u] = __expf(z - c);
            sum += e[u];
            es[(j + u) * 9 + wr] = e[u];
        }
        __half h0 = __float2half(e[0]), h1 = __float2half(e[1]);
        __half h2 = __float2half(e[2]), h3 = __float2half(e[3]);
        uint2 hv;
        hv.x = ((uint32_t)*(uint16_t*)&h1 << 16) | *(uint16_t*)&h0;
        hv.y = ((uint32_t)*(uint16_t*)&h3 << 16) | *(uint16_t*)&h2;
        *(uint2*)&g_Ahi[(size_t)irow * NN + j] = hv;
    }
    #pragma unroll
    for (int o = 16; o > 0; o >>= 1) sum += __shfl_xor_sync(0xffffffffu, sum, o);
    if (lane == 0) {
        float si = 1.f / sum;
        s_si[wr] = si;
        g_si[irow] = si;
    }
    __syncthreads();

    // transposed f32 write: att[b][j][i0..i0+7]
    int half = tid & 1, jb = tid >> 1;
    float si4[4];
    #pragma unroll
    for (int u = 0; u < 4; u++) si4[u] = s_si[half * 4 + u];
    #pragma unroll
    for (int kk = 0; kk < 8; kk++) {
        int j = jb + 128 * kk;
        float4 pv;
        pv.x = es[j * 9 + half * 4 + 0] * si4[0];
        pv.y = es[j * 9 + half * 4 + 1] * si4[1];
        pv.z = es[j * 9 + half * 4 + 2] * si4[2];
        pv.w = es[j * 9 + half * 4 + 3] * si4[3];
        *(float4*)&outAtt[(((size_t)(b << 10) + j)) * NN + i0 + half * 4] = pv;
    }
}

// ------------------------------------------------------------------
// Kernel 4: HMMA fp16 GEMM; epilogue scales row q by si[q]
// ------------------------------------------------------------------
#define STAGE_BYTES (32 * 1024)
#define XT_OFF      (16 * 1024)
#define NCHUNK      16

__device__ __forceinline__ void issue_stage(uint32_t sb,
    const __half* Ah, const __half* Xh, int k0, int tid)
{
    int cm = tid >> 3;
    int cu = tid & 7;
    int kc = cu * 8;
    #pragma unroll
    for (int r = 0; r < 4; r++) {
        int m = cm + 32 * r;
        uint32_t sw = (uint32_t)((cu ^ (m & 7)) << 4);
        cp16(sb + m * 128 + sw,          Ah + (size_t)m * NN + k0 + kc);
        cp16(sb + XT_OFF + m * 128 + sw, Xh + (size_t)m * NN + k0 + kc);
    }
}

__global__ __launch_bounds__(256, 2) void gemm_hmma_kernel(float* __restrict__ out)
{
    extern __shared__ char smc[];
    int tid  = threadIdx.x;
    int lane = tid & 31, w = tid >> 5;
    int b  = blockIdx.z;
    int n0 = blockIdx.x * 128;
    int m0 = blockIdx.y * 128;

    const __half* Ah = g_Ahi + ((size_t)(b * NN + m0)) * NN;
    const __half* Xh = g_Xh  + ((size_t)(b * CL + n0)) * NN;

    uint32_t smb = smem_u32(smc);

    issue_stage(smb, Ah, Xh, 0, tid);
    cp_commit();
    issue_stage(smb + STAGE_BYTES, Ah, Xh, 64, tid);
    cp_commit();

    int wm = (w & 3) * 32;
    int wn = (w >> 2) * 64;

    float acc[2][8][4];
    #pragma unroll
    for (int t = 0; t < 2; t++)
        #pragma unroll
        for (int bk = 0; bk < 8; bk++)
            #pragma unroll
            for (int e = 0; e < 4; e++) acc[t][bk][e] = 0.f;

    int ai  = lane & 15, ahf = lane >> 4;
    int xcb = (lane >> 4) & 1, xkh = (lane >> 3) & 1, xc7 = lane & 7;

    for (int t = 0; t < NCHUNK; t++) {
        cp_wait1();
        __syncthreads();

        uint32_t sa = smb + (t % 3) * STAGE_BYTES;
        uint32_t sx = sa + XT_OFF;

        #pragma unroll
        for (int s = 0; s < 4; s++) {
            uint32_t ah[2][4];
            #pragma unroll
            for (int mt = 0; mt < 2; mt++) {
                int row = wm + mt * 16 + ai;
                int cuH = 2 * s + ahf;
                ldsm4(ah[mt], sa + row * 128 + ((cuH ^ (row & 7)) << 4));
            }
            #pragma unroll
            for (int g = 0; g < 4; g++) {
                uint32_t xh[4];
                int col = wn + g * 16 + xcb * 8 + xc7;
                int cuH = 2 * s + xkh;
                ldsm4(xh, sx + col * 128 + ((cuH ^ (col & 7)) << 4));
                #pragma unroll
                for (int mt = 0; mt < 2; mt++) {
                    mma16816(acc[mt][2 * g],     ah[mt], &xh[0]);
                    mma16816(acc[mt][2 * g + 1], ah[mt], &xh[2]);
                }
            }
            if (s == 0) {
                if (t + 2 < NCHUNK)
                    issue_stage(smb + ((t + 2) % 3) * STAGE_BYTES, Ah, Xh, (t + 2) * 64, tid);
                cp_commit();
            }
        }
    }

    // epilogue: scale by si[q], scatter to out[b][c][q][l]
    float* ob = out + (size_t)b * COUT * NN * LL;
    int g8 = lane >> 2, t4 = lane & 3;
    float sv[2][2];
    #pragma unroll
    for (int mt = 0; mt < 2; mt++)
        #pragma unroll
        for (int r = 0; r < 2; r++)
            sv[mt][r] = __ldg(&g_si[(size_t)b * NN + m0 + wm + mt * 16 + g8 + r * 8]);
    #pragma unroll
    for (int mt = 0; mt < 2; mt++) {
        int q0 = m0 + wm + mt * 16 + g8;
        #pragma unroll
        for (int bk = 0; bk < 8; bk++) {
            int cl0 = n0 + wn + bk * 8 + t4 * 2;
            #pragma unroll
            for (int e = 0; e < 4; e++) {
                int q  = q0 + (e >> 1) * 8;
                int cl = cl0 + (e & 1);
                int c = cl / 12, l = cl - c * 12;
                ob[(size_t)c * (NN * LL) + q * 12 + l] = acc[mt][bk][e] * sv[mt][e >> 1];
            }
        }
    }
}

// ------------------------------------------------------------------
extern "C" void kernel_launch(void* const* d_in, const int* in_sizes, int n_in,
                              void* d_out, int out_size)
{
    const float* in  = (const float*)d_in[0];
    const float* adj = (const float*)d_in[1];
    const float* w0  = (const float*)d_in[2];
    const float* b0  = (const float*)d_in[3];
    const float* w1  = (const float*)d_in[4];

    float* out    = (float*)d_out;
    float* hprime = out;
    float* att    = out + (size_t)BB * COUT * NN * LL;

    cudaFuncSetAttribute(convmma_kernel, cudaFuncAttributeMaxDynamicSharedMemorySize, CSMEM);
    cudaFuncSetAttribute(smax_kernel, cudaFuncAttributeMaxDynamicSharedMemorySize, SMAX_SMEM);
    cudaFuncSetAttribute(gemm_hmma_kernel, cudaFuncAttributeMaxDynamicSharedMemorySize, 3 * STAGE_BYTES);

    weff_kernel<<<1, 768>>>(w0, b0, w1);
    convmma_kernel<<<dim3(NN / 8, BB), 256, CSMEM>>>(in, b0);
    fmax_kernel<<<BB, 256>>>();
    smax_kernel<<<dim3(NN / 8, BB), 256, SMAX_SMEM>>>(adj, att);
    gemm_hmma_kernel<<<dim3(CL / 128, NN / 128, BB), 256, 3 * STAGE_BYTES>>>(hprime);
}

// round 17
// speedup vs baseline: 1.9738x; 1.0417x over previous
#include <cuda_runtime.h>
#include <cuda_fp16.h>
#include <cstdint>

#define BB   16
#define CIN  64
#define COUT 64
#define NN   1024
#define LL   12
#define CL   768   // COUT*LL

// ------------------- device scratch (allocation-free) -------------------
__device__ float g_f   [(size_t)BB * NN];
__device__ float g_fmax[BB];
__device__ float g_si  [(size_t)BB * NN];     // 1 / sum(e') per row
__device__ float g_weff[CIN * 12];
__device__ float g_fconst;
__device__ __align__(16) __half g_Wh [(size_t)COUT * 192];   // [cout][kt*64+cin]
__device__ __align__(16) __half g_Ahi[(size_t)BB * NN * NN]; // [b][q][n] unnormalized e'
__device__ __align__(16) __half g_Xh [(size_t)BB * CL * NN]; // [b][cl][n]

// ------------------- PTX helpers -------------------
__device__ __forceinline__ uint32_t smem_u32(const void* p) {
    uint32_t a;
    asm("{ .reg .u64 t; cvta.to.shared.u64 t, %1; cvt.u32.u64 %0, t; }" : "=r"(a) : "l"(p));
    return a;
}
__device__ __forceinline__ void cp16(uint32_t dst, const void* src) {
    asm volatile("cp.async.cg.shared.global [%0], [%1], 16;" :: "r"(dst), "l"(src));
}
__device__ __forceinline__ void cp_commit() {
    asm volatile("cp.async.commit_group;" ::: "memory");
}
__device__ __forceinline__ void cp_wait1() {
    asm volatile("cp.async.wait_group 1;" ::: "memory");
}
__device__ __forceinline__ void cp_wait0() {
    asm volatile("cp.async.wait_group 0;" ::: "memory");
}
__device__ __forceinline__ void ldsm4(uint32_t* r, uint32_t addr) {
    asm volatile("ldmatrix.sync.aligned.m8n8.x4.shared.b16 {%0,%1,%2,%3}, [%4];"
                 : "=r"(r[0]), "=r"(r[1]), "=r"(r[2]), "=r"(r[3]) : "r"(addr));
}
__device__ __forceinline__ void mma16816(float* d, const uint32_t* a, const uint32_t* bf) {
    asm volatile(
        "mma.sync.aligned.m16n8k16.row.col.f32.f16.f16.f32 "
        "{%0,%1,%2,%3}, {%4,%5,%6,%7}, {%8,%9}, {%0,%1,%2,%3};"
        : "+f"(d[0]), "+f"(d[1]), "+f"(d[2]), "+f"(d[3])
        : "r"(a[0]), "r"(a[1]), "r"(a[2]), "r"(a[3]), "r"(bf[0]), "r"(bf[1]));
}

// ------------------------------------------------------------------
// Kernel 0: effective f-weights + fp16 weight matrix (kt-major k order)
// ------------------------------------------------------------------
__global__ void weff_kernel(const float* __restrict__ w0,
                            const float* __restrict__ b0,
                            const float* __restrict__ w1)
{
    int t = threadIdx.x;              // 768
    int cin = t / 12, lp = t % 12;
    float s = 0.f;
    for (int c = 0; c < COUT; c++) {
        #pragma unroll
        for (int kt = 0; kt < 3; kt++) {
            int l = lp - kt + 1;
            if (l >= 0 && l < 12)
                s += w0[c * 192 + cin * 3 + kt] * w1[c * 12 + l];
        }
    }
    g_weff[t] = s;
    // reorder k: [cin*3+kt] -> [kt*64+cin]
    for (int idx = t; idx < COUT * 192; idx += 768) {
        int cout = idx / 192, k = idx % 192;
        int kt = k / 64, ci = k % 64;
        g_Wh[idx] = __float2half(w0[cout * 192 + ci * 3 + kt]);
    }
    if (t == 0) {
        float fc = 0.f;
        for (int c = 0; c < COUT; c++) {
            float sw = 0.f;
            for (int l = 0; l < 12; l++) sw += w1[c * 12 + l];
            fc += b0[c] * sw;
        }
        g_fconst = fc;
    }
}

// ------------------------------------------------------------------
// Kernel 1: conv as HMMA im2col GEMM; kt-major k order (coalesced STS)
// B[(n,l)][kt*64+cin] = v(cin, l+kt-1)
// ------------------------------------------------------------------
#define CPITCH 400
#define B_OFF  (64 * CPITCH)
#define WF_OFF (B_OFF + 96 * CPITCH)
#define CSMEM  (WF_OFF + 768 * 4 + 128)

__global__ __launch_bounds__(256) void convmma_kernel(
    const float* __restrict__ in, const float* __restrict__ b0)
{
    extern __shared__ char cs[];
    uint32_t sb = smem_u32(cs);
    int tid = threadIdx.x;
    int lane = tid & 31, w = tid >> 5;
    int b  = blockIdx.y;
    int n0 = blockIdx.x * 8;

    // phase 1a: async weight copy (fp16, 64 rows x 384B)
    for (int idx = tid; idx < 1536; idx += 256) {
        int cout = idx / 24, k = idx % 24;
        cp16(sb + cout * CPITCH + k * 16, &g_Wh[cout * 192 + k * 8]);
    }
    cp_commit();
    // phase 1b: weff to smem + contiguous boundary zeros
    for (int idx = tid; idx < 768; idx += 256)
        *(float*)(cs + WF_OFF + idx * 4) = g_weff[idx];
    uint4 zz = make_uint4(0, 0, 0, 0);
    for (int idx = tid; idx < 128; idx += 256) {   // only tid<128 active once
        int gid = (idx & 63) >> 3, u = idx & 7;
        int row = (idx < 64) ? gid * 12 : gid * 12 + 11;
        int off = (idx < 64) ? u * 16 : 256 + u * 16;
        *(uint4*)(cs + B_OFF + row * CPITCH + off) = zz;
    }
    __syncthreads();   // weff visible for phase 2

    // phase 2: im2col fill (fp16, coalesced) + f (fp32)
    {
        int gid = tid >> 5;
        const float* weffS = (const float*)(cs + WF_OFF);
        float fp = 0.f;
        #pragma unroll
        for (int c2 = 0; c2 < 2; c2++) {
            int cin = lane + 32 * c2;
            const float* src = in + ((size_t)b * CIN + cin) * (NN * LL) + (size_t)(n0 + gid) * LL;
            float4 v0 = *(const float4*)(src);
            float4 v1 = *(const float4*)(src + 4);
            float4 v2 = *(const float4*)(src + 8);
            float v[12] = {v0.x, v0.y, v0.z, v0.w, v1.x, v1.y, v1.z, v1.w,
                           v2.x, v2.y, v2.z, v2.w};
            #pragma unroll
            for (int lp = 0; lp < 12; lp++) {
                fp += v[lp] * weffS[cin * 12 + lp];
                __half h = __float2half(v[lp]);
                // kt=1 -> row lp, col 64+cin
                *(__half*)(cs + B_OFF + (gid * 12 + lp) * CPITCH + (64 + cin) * 2) = h;
                if (lp <= 10)  // kt=0 -> row lp+1, col cin
                    *(__half*)(cs + B_OFF + (gid * 12 + lp + 1) * CPITCH + cin * 2) = h;
                if (lp >= 1)   // kt=2 -> row lp-1, col 128+cin
                    *(__half*)(cs + B_OFF + (gid * 12 + lp - 1) * CPITCH + (128 + cin) * 2) = h;
            }
        }
        #pragma unroll
        for (int o = 16; o > 0; o >>= 1) fp += __shfl_xor_sync(0xffffffffu, fp, o);
        if (lane == 0) g_f[b * NN + n0 + gid] = fp + g_fconst;
    }
    cp_wait0();
    __syncthreads();

    // phase 3: MMA — warp tile 16(m) x 48(n), K=192
    int wm16 = (w & 3) * 16;
    int wn48 = (w >> 2) * 48;
    float acc[6][4];
    #pragma unroll
    for (int bk = 0; bk < 6; bk++)
        #pragma unroll
        for (int e = 0; e < 4; e++) acc[bk][e] = 0.f;

    int ai = lane & 15, ahf = lane >> 4;
    int xcb = (lane >> 4) & 1, xkh = (lane >> 3) & 1, xc7 = lane & 7;

    #pragma unroll
    for (int s = 0; s < 12; s++) {
        uint32_t af[4];
        ldsm4(af, sb + (wm16 + ai) * CPITCH + (2 * s + ahf) * 16);
        #pragma unroll
        for (int g = 0; g < 3; g++) {
            uint32_t xf[4];
            int col = wn48 + g * 16 + xcb * 8 + xc7;
            ldsm4(xf, sb + B_OFF + col * CPITCH + (2 * s + xkh) * 16);
            mma16816(acc[2 * g],     af, &xf[0]);
            mma16816(acc[2 * g + 1], af, &xf[2]);
        }
    }
    __syncthreads();

    // phase 4: bias + stage
    __half* stg = (__half*)(cs + B_OFF);
    #pragma unroll
    for (int bk = 0; bk < 6; bk++) {
        #pragma unroll
        for (int e = 0; e < 4; e++) {
            int m   = wm16 + (lane >> 2) + 8 * (e >> 1);
            int col = wn48 + bk * 8 + (lane & 3) * 2 + (e & 1);
            stg[m * 100 + col] = __float2half(acc[bk][e] + __ldg(&b0[m]));
        }
    }
    __syncthreads();

    // phase 5: write X^T
    for (int idx = tid; idx < 768; idx += 256) {
        int cout = idx / 12, l = idx % 12;
        __half tmp[8];
        #pragma unroll
        for (int nl = 0; nl < 8; nl++) tmp[nl] = stg[cout * 100 + nl * 12 + l];
        *(uint4*)&g_Xh[((size_t)b * CL + cout * 12 + l) * NN + n0] = *(uint4*)tmp;
    }
}

// ------------------------------------------------------------------
// Kernel 2: per-batch max of f
// ------------------------------------------------------------------
__global__ __launch_bounds__(256) void fmax_kernel()
{
    int b = blockIdx.x, tid = threadIdx.x;
    const float* fb = g_f + b * NN;
    float m = -1e30f;
    #pragma unroll
    for (int k = 0; k < 4; k++) m = fmaxf(m, fb[tid + k * 256]);
    __shared__ float sred[8];
    #pragma unroll
    for (int o = 16; o > 0; o >>= 1) m = fmaxf(m, __shfl_xor_sync(0xffffffffu, m, o));
    if ((tid & 31) == 0) sred[tid >> 5] = m;
    __syncthreads();
    if (tid == 0) {
        float v = sred[0];
        #pragma unroll
        for (int k = 1; k < 8; k++) v = fmaxf(v, sred[k]);
        g_fmax[b] = v;
    }
}

// ------------------------------------------------------------------
// Kernel 3: fused softmax. Block = 8 full rows (one warp per row).
// es row-major [8][EPITCH] f32; STS.128 writes, conflict-free reads.
// ------------------------------------------------------------------
#define EPITCH 1028                     // mod 32 == 4 -> conflict-free transpose
#define SMAX_SMEM (8 * EPITCH * 4)

__global__ __launch_bounds__(256) void smax_kernel(
    const float* __restrict__ adj, float* __restrict__ outAtt)
{
    extern __shared__ float es[];     // [8][EPITCH]
    __shared__ float s_si[8];
    int b  = blockIdx.y;
    int i0 = blockIdx.x * 8;
    int tid = threadIdx.x;
    int lane = tid & 31, wr = tid >> 5;     // wr = local row

    const float* fb = g_f + b * NN;
    int irow = (b << 10) + i0 + wr;
    float fi = fb[i0 + wr];
    float c  = fi + g_fmax[b] + 1.0f;
    const float* arow = adj + (size_t)irow * NN;

    float sum = 0.f;
    #pragma unroll
    for (int kk = 0; kk < 8; kk++) {
        int j = lane * 4 + kk * 128;
        float4 av = *(const float4*)&arow[j];
        float4 e4;
        float* e = (float*)&e4;
        #pragma unroll
        for (int u = 0; u < 4; u++) {
            float lg = fi + fb[j + u];
            float z  = (lg >= 0.f ? lg : 0.2f * lg) + ((const float*)&av)[u];
            e[u] = __expf(z - c);
            sum += e[u];
        }
        *(float4*)&es[wr * EPITCH + j] = e4;         // STS.128
        __half h0 = __float2half(e[0]), h1 = __float2half(e[1]);
        __half h2 = __float2half(e[2]), h3 = __float2half(e[3]);
        uint2 hv;
        hv.x = ((uint32_t)*(uint16_t*)&h1 << 16) | *(uint16_t*)&h0;
        hv.y = ((uint32_t)*(uint16_t*)&h3 << 16) | *(uint16_t*)&h2;
        *(uint2*)&g_Ahi[(size_t)irow * NN + j] = hv;
    }
    #pragma unroll
    for (int o = 16; o > 0; o >>= 1) sum += __shfl_xor_sync(0xffffffffu, sum, o);
    if (lane == 0) {
        float si = 1.f / sum;
        s_si[wr] = si;
        g_si[irow] = si;
    }
    __syncthreads();

    // transposed f32 write: att[b][j][i0..i0+7]
    int half = tid & 1, jb = tid >> 1;
    float si4[4];
    #pragma unroll
    for (int u = 0; u < 4; u++) si4[u] = s_si[half * 4 + u];
    #pragma unroll
    for (int kk = 0; kk < 8; kk++) {
        int j = jb + 128 * kk;
        float4 pv;
        pv.x = es[(half * 4 + 0) * EPITCH + j] * si4[0];
        pv.y = es[(half * 4 + 1) * EPITCH + j] * si4[1];
        pv.z = es[(half * 4 + 2) * EPITCH + j] * si4[2];
        pv.w = es[(half * 4 + 3) * EPITCH + j] * si4[3];
        *(float4*)&outAtt[(((size_t)(b << 10) + j)) * NN + i0 + half * 4] = pv;
    }
}

// ------------------------------------------------------------------
// Kernel 4: HMMA fp16 GEMM; epilogue scales row q by si[q]
// ------------------------------------------------------------------
#define STAGE_BYTES (32 * 1024)
#define XT_OFF      (16 * 1024)
#define NCHUNK      16

__device__ __forceinline__ void issue_stage(uint32_t sb,
    const __half* Ah, const __half* Xh, int k0, int tid)
{
    int cm = tid >> 3;
    int cu = tid & 7;
    int kc = cu * 8;
    #pragma unroll
    for (int r = 0; r < 4; r++) {
        int m = cm + 32 * r;
        uint32_t sw = (uint32_t)((cu ^ (m & 7)) << 4);
        cp16(sb + m * 128 + sw,          Ah + (size_t)m * NN + k0 + kc);
        cp16(sb + XT_OFF + m * 128 + sw, Xh + (size_t)m * NN + k0 + kc);
    }
}

__global__ __launch_bounds__(256, 2) void gemm_hmma_kernel(float* __restrict__ out)
{
    extern __shared__ char smc[];
    int tid  = threadIdx.x;
    int lane = tid & 31, w = tid >> 5;
    int b  = blockIdx.z;
    int n0 = blockIdx.x * 128;
    int m0 = blockIdx.y * 128;

    const __half* Ah = g_Ahi + ((size_t)(b * NN + m0)) * NN;
    const __half* Xh = g_Xh  + ((size_t)(b * CL + n0)) * NN;

    uint32_t smb = smem_u32(smc);

    issue_stage(smb, Ah, Xh, 0, tid);
    cp_commit();
    issue_stage(smb + STAGE_BYTES, Ah, Xh, 64, tid);
    cp_commit();

    int wm = (w & 3) * 32;
    int wn = (w >> 2) * 64;

    float acc[2][8][4];
    #pragma unroll
    for (int t = 0; t < 2; t++)
        #pragma unroll
        for (int bk = 0; bk < 8; bk++)
            #pragma unroll
            for (int e = 0; e < 4; e++) acc[t][bk][e] = 0.f;

    int ai  = lane & 15, ahf = lane >> 4;
    int xcb = (lane >> 4) & 1, xkh = (lane >> 3) & 1, xc7 = lane & 7;

    for (int t = 0; t < NCHUNK; t++) {
        cp_wait1();
        __syncthreads();

        uint32_t sa = smb + (t % 3) * STAGE_BYTES;
        uint32_t sx = sa + XT_OFF;

        #pragma unroll
        for (int s = 0; s < 4; s++) {
            uint32_t ah[2][4];
            #pragma unroll
            for (int mt = 0; mt < 2; mt++) {
                int row = wm + mt * 16 + ai;
                int cuH = 2 * s + ahf;
                ldsm4(ah[mt], sa + row * 128 + ((cuH ^ (row & 7)) << 4));
            }
            #pragma unroll
            for (int g = 0; g < 4; g++) {
                uint32_t xh[4];
                int col = wn + g * 16 + xcb * 8 + xc7;
                int cuH = 2 * s + xkh;
                ldsm4(xh, sx + col * 128 + ((cuH ^ (col & 7)) << 4));
                #pragma unroll
                for (int mt = 0; mt < 2; mt++) {
                    mma16816(acc[mt][2 * g],     ah[mt], &xh[0]);
                    mma16816(acc[mt][2 * g + 1], ah[mt], &xh[2]);
                }
            }
            if (s == 0) {
                if (t + 2 < NCHUNK)
                    issue_stage(smb + ((t + 2) % 3) * STAGE_BYTES, Ah, Xh, (t + 2) * 64, tid);
                cp_commit();
            }
        }
    }

    // epilogue: scale by si[q], scatter to out[b][c][q][l]
    float* ob = out + (size_t)b * COUT * NN * LL;
    int g8 = lane >> 2, t4 = lane & 3;
    float sv[2][2];
    #pragma unroll
    for (int mt = 0; mt < 2; mt++)
        #pragma unroll
        for (int r = 0; r < 2; r++)
            sv[mt][r] = __ldg(&g_si[(size_t)b * NN + m0 + wm + mt * 16 + g8 + r * 8]);
    #pragma unroll
    for (int mt = 0; mt < 2; mt++) {
        int q0 = m0 + wm + mt * 16 + g8;
        #pragma unroll
        for (int bk = 0; bk < 8; bk++) {
            int cl0 = n0 + wn + bk * 8 + t4 * 2;
            #pragma unroll
            for (int e = 0; e < 4; e++) {
                int q  = q0 + (e >> 1) * 8;
                int cl = cl0 + (e & 1);
                int c = cl / 12, l = cl - c * 12;
                ob[(size_t)c * (NN * LL) + q * 12 + l] = acc[mt][bk][e] * sv[mt][e >> 1];
            }
        }
    }
}

// ------------------------------------------------------------------
extern "C" void kernel_launch(void* const* d_in, const int* in_sizes, int n_in,
                              void* d_out, int out_size)
{
    const float* in  = (const float*)d_in[0];
    const float* adj = (const float*)d_in[1];
    const float* w0  = (const float*)d_in[2];
    const float* b0  = (const float*)d_in[3];
    const float* w1  = (const float*)d_in[4];

    float* out    = (float*)d_out;
    float* hprime = out;
    float* att    = out + (size_t)BB * COUT * NN * LL;

    cudaFuncSetAttribute(convmma_kernel, cudaFuncAttributeMaxDynamicSharedMemorySize, CSMEM);
    cudaFuncSetAttribute(smax_kernel, cudaFuncAttributeMaxDynamicSharedMemorySize, SMAX_SMEM);
    cudaFuncSetAttribute(gemm_hmma_kernel, cudaFuncAttributeMaxDynamicSharedMemorySize, 3 * STAGE_BYTES);

    weff_kernel<<<1, 768>>>(w0, b0, w1);
    convmma_kernel<<<dim3(NN / 8, BB), 256, CSMEM>>>(in, b0);
    fmax_kernel<<<BB, 256>>>();
    smax_kernel<<<dim3(NN / 8, BB), 256, SMAX_SMEM>>>(adj, att);
    gemm_hmma_kernel<<<dim3(CL / 128, NN / 128, BB), 256, 3 * STAGE_BYTES>>>(hprime);
}